// round 1
// baseline (speedup 1.0000x reference)
#include <cuda_runtime.h>
#include <cstdint>
#include <math.h>

#define S_LEN   2048
#define HIDDEN  4096
#define NHEADS  32
#define NKV     8
#define HD      128
#define QPK     4
#define QKV_N   6144          // NKV*(QPK+2)*HD
#define OUT_N   4096          // NHEADS*HD
#define SCALE_ATT 0.0078125f  // 1/HD

// ---------------- scratch (device globals: no allocations allowed) ----------
__device__ float g_qkv[S_LEN * QKV_N];   // 50 MB
__device__ float g_att[S_LEN * OUT_N];   // 32 MB
__device__ float g_cos[S_LEN * 64];
__device__ float g_sin[S_LEN * 64];

// ---------------------------------------------------------------------------
// SGEMM: C[M,N] = A[M,K] @ B[N,K]^T + bias[N]     (both operands K-major)
// 128x128 block tile, BK=16, 256 threads, 8x8 microtile split in 4x(4x4).
// ---------------------------------------------------------------------------
__global__ __launch_bounds__(256) void sgemm_bt_bias(
    const float* __restrict__ A, const float* __restrict__ B,
    const float* __restrict__ bias, float* __restrict__ C,
    int M, int N, int K)
{
    __shared__ float As[16][128];
    __shared__ float Bs[16][128];

    const int m0 = blockIdx.y * 128;
    const int n0 = blockIdx.x * 128;
    const int tid = threadIdx.x;
    const int tx = tid & 15;       // col group
    const int ty = tid >> 4;       // row group
    const int lr = tid >> 1;       // 0..127 : tile row this thread loads
    const int lk = (tid & 1) * 8;  // k offset 0 or 8 (8 consecutive floats)

    const float* Ap = A + (size_t)(m0 + lr) * K + lk;
    const float* Bp = B + (size_t)(n0 + lr) * K + lk;

    float acc[2][2][4][4];
#pragma unroll
    for (int a = 0; a < 2; a++)
#pragma unroll
        for (int b = 0; b < 2; b++)
#pragma unroll
            for (int i = 0; i < 4; i++)
#pragma unroll
                for (int j = 0; j < 4; j++) acc[a][b][i][j] = 0.0f;

    for (int kt = 0; kt < K; kt += 16) {
        float4 a0 = *(const float4*)(Ap + kt);
        float4 a1 = *(const float4*)(Ap + kt + 4);
        float4 b0 = *(const float4*)(Bp + kt);
        float4 b1 = *(const float4*)(Bp + kt + 4);
        __syncthreads();
        As[lk + 0][lr] = a0.x; As[lk + 1][lr] = a0.y;
        As[lk + 2][lr] = a0.z; As[lk + 3][lr] = a0.w;
        As[lk + 4][lr] = a1.x; As[lk + 5][lr] = a1.y;
        As[lk + 6][lr] = a1.z; As[lk + 7][lr] = a1.w;
        Bs[lk + 0][lr] = b0.x; Bs[lk + 1][lr] = b0.y;
        Bs[lk + 2][lr] = b0.z; Bs[lk + 3][lr] = b0.w;
        Bs[lk + 4][lr] = b1.x; Bs[lk + 5][lr] = b1.y;
        Bs[lk + 6][lr] = b1.z; Bs[lk + 7][lr] = b1.w;
        __syncthreads();
#pragma unroll
        for (int k = 0; k < 16; k++) {
            float4 aL = *(const float4*)&As[k][ty * 4];
            float4 aH = *(const float4*)&As[k][64 + ty * 4];
            float4 bL = *(const float4*)&Bs[k][tx * 4];
            float4 bH = *(const float4*)&Bs[k][64 + tx * 4];
            float av[2][4] = {{aL.x, aL.y, aL.z, aL.w}, {aH.x, aH.y, aH.z, aH.w}};
            float bv[2][4] = {{bL.x, bL.y, bL.z, bL.w}, {bH.x, bH.y, bH.z, bH.w}};
#pragma unroll
            for (int a = 0; a < 2; a++)
#pragma unroll
                for (int b = 0; b < 2; b++)
#pragma unroll
                    for (int i = 0; i < 4; i++)
#pragma unroll
                        for (int j = 0; j < 4; j++)
                            acc[a][b][i][j] += av[a][i] * bv[b][j];
        }
    }

#pragma unroll
    for (int a = 0; a < 2; a++) {
#pragma unroll
        for (int i = 0; i < 4; i++) {
            int m = m0 + a * 64 + ty * 4 + i;
            float* Crow = C + (size_t)m * N;
#pragma unroll
            for (int b = 0; b < 2; b++) {
                int n = n0 + b * 64 + tx * 4;
                float4 bb = *(const float4*)(bias + n);
                float4 o;
                o.x = acc[a][b][i][0] + bb.x;
                o.y = acc[a][b][i][1] + bb.y;
                o.z = acc[a][b][i][2] + bb.z;
                o.w = acc[a][b][i][3] + bb.w;
                *(float4*)(Crow + n) = o;
            }
        }
    }
}

// ---------------------------------------------------------------------------
// RoPE tables: cos/sin of fp32(pos * fp32(inv_freq)) computed via fp64 trig
// (safe against --use_fast_math range reduction at args up to ~2047 rad).
// ---------------------------------------------------------------------------
__global__ void cs_table_kernel(const int* __restrict__ positions)
{
    int idx = blockIdx.x * blockDim.x + threadIdx.x;
    if (idx >= S_LEN * 64) return;
    int i = idx & 63;
    int s = idx >> 6;
    float pos = (float)positions[s];
    double e = (double)(2 * i) / 128.0;
    float invf = (float)(1.0 / pow(1.0e6, e));
    float freq = pos * invf;                 // fp32 rounding, matches jax
    g_cos[idx] = (float)cos((double)freq);
    g_sin[idx] = (float)sin((double)freq);
}

// RoPE applied in-place to q slots 0..3 and k slot 4 (v untouched).
__global__ void rope_apply_kernel()
{
    int idx = blockIdx.x * blockDim.x + threadIdx.x;   // < S*NKV*5*64
    int i = idx & 63;
    int t = idx >> 6;
    int slot = t % 5;
    t /= 5;
    int kvh = t & 7;
    int s = t >> 3;
    float c  = g_cos[(s << 6) | i];
    float sn = g_sin[(s << 6) | i];
    size_t base = (size_t)s * QKV_N + kvh * 768 + slot * 128 + i;
    float x1 = g_qkv[base];
    float x2 = g_qkv[base + 64];
    g_qkv[base]      = x1 * c - x2 * sn;
    g_qkv[base + 64] = x2 * c + x1 * sn;
}

// ---------------------------------------------------------------------------
// Blocksparse flash attention. CTA = (q-block of 64 rows, head). 256 threads.
// k-block (64) allowed iff (qb-kb < 16) || ((kb+h+1)%8==0), kb<=qb; elementwise
// causal only on the diagonal block. GQA: head h uses kv head h/4.
// smem: Qt[128][64], Kt[128][64] (d-major), Vs[64][128], Ps[64][64] = 112 KB.
// ---------------------------------------------------------------------------
__global__ __launch_bounds__(256) void attn_kernel(float* __restrict__ out)
{
    extern __shared__ float sm[];
    float* Qt = sm;                  // [128][64]
    float* Kt = Qt + 128 * 64;       // [128][64]
    float* Vs = Kt + 128 * 64;       // [64][128]
    float* Ps = Vs + 64 * 128;       // [64][64]

    const int qb = blockIdx.x;
    const int h  = blockIdx.y;
    const int kvh = h >> 2, slot = h & 3;
    const int tid = threadIdx.x;
    const int tx = tid & 15;         // S col group
    const int ty = tid >> 4;         // S row group
    const int q0 = qb * 64;
    const int lr  = tid >> 2;        // 0..63 : row loaded by this thread
    const int lf0 = tid & 3;         // starting float4 index along d

    const size_t qoff = (size_t)kvh * 768 + slot * 128;
    const size_t koff = (size_t)kvh * 768 + 512;  // slot 4
    const size_t voff = (size_t)kvh * 768 + 640;  // slot 5

    // Q -> Qt (transposed)
#pragma unroll
    for (int it = 0; it < 8; it++) {
        int f = lf0 + it * 4;
        float4 v = *(const float4*)(g_qkv + (size_t)(q0 + lr) * QKV_N + qoff + f * 4);
        Qt[(f * 4 + 0) * 64 + lr] = v.x;
        Qt[(f * 4 + 1) * 64 + lr] = v.y;
        Qt[(f * 4 + 2) * 64 + lr] = v.z;
        Qt[(f * 4 + 3) * 64 + lr] = v.w;
    }

    float o[4][8];
#pragma unroll
    for (int i = 0; i < 4; i++)
#pragma unroll
        for (int c = 0; c < 8; c++) o[i][c] = 0.0f;
    float mrow[4] = {-1e30f, -1e30f, -1e30f, -1e30f};
    float lrow[4] = {0.0f, 0.0f, 0.0f, 0.0f};

    for (int kb = 0; kb <= qb; kb++) {
        bool allowed = ((qb - kb) < 16) || (((kb + h + 1) & 7) == 0);
        if (!allowed) continue;
        __syncthreads();   // prior PV reads of Kt/Vs/Ps done before overwrite
        int k0 = kb * 64;
        // K -> Kt (transposed)
#pragma unroll
        for (int it = 0; it < 8; it++) {
            int f = lf0 + it * 4;
            float4 v = *(const float4*)(g_qkv + (size_t)(k0 + lr) * QKV_N + koff + f * 4);
            Kt[(f * 4 + 0) * 64 + lr] = v.x;
            Kt[(f * 4 + 1) * 64 + lr] = v.y;
            Kt[(f * 4 + 2) * 64 + lr] = v.z;
            Kt[(f * 4 + 3) * 64 + lr] = v.w;
        }
        // V straight copy
#pragma unroll
        for (int it = 0; it < 8; it++) {
            int idx = tid + it * 256;          // float4 index < 2048
            int r = idx >> 5, f = idx & 31;
            *(float4*)(Vs + r * 128 + f * 4) =
                *(const float4*)(g_qkv + (size_t)(k0 + r) * QKV_N + voff + f * 4);
        }
        __syncthreads();

        // S = Q @ K^T  (4x4 per thread over d=128)
        float s_acc[4][4];
#pragma unroll
        for (int i = 0; i < 4; i++)
#pragma unroll
            for (int j = 0; j < 4; j++) s_acc[i][j] = 0.0f;
#pragma unroll 4
        for (int d = 0; d < 128; d++) {
            float4 a = *(const float4*)&Qt[d * 64 + ty * 4];
            float4 b = *(const float4*)&Kt[d * 64 + tx * 4];
            float av[4] = {a.x, a.y, a.z, a.w};
            float bv[4] = {b.x, b.y, b.z, b.w};
#pragma unroll
            for (int i = 0; i < 4; i++)
#pragma unroll
                for (int j = 0; j < 4; j++) s_acc[i][j] += av[i] * bv[j];
        }

        const bool diag = (kb == qb);
#pragma unroll
        for (int i = 0; i < 4; i++) {
            int r = ty * 4 + i;
            float sv[4];
#pragma unroll
            for (int j = 0; j < 4; j++) {
                int c = tx * 4 + j;
                float v = s_acc[i][j] * SCALE_ATT;
                if (diag && c > r) v = -1e30f;
                sv[j] = v;
            }
            float mb = fmaxf(fmaxf(sv[0], sv[1]), fmaxf(sv[2], sv[3]));
#pragma unroll
            for (int off = 8; off; off >>= 1)
                mb = fmaxf(mb, __shfl_xor_sync(0xffffffffu, mb, off));
            float mnew = fmaxf(mrow[i], mb);
            float corr = __expf(mrow[i] - mnew);
            float p[4];
#pragma unroll
            for (int j = 0; j < 4; j++) p[j] = __expf(sv[j] - mnew);
            *(float4*)&Ps[r * 64 + tx * 4] = make_float4(p[0], p[1], p[2], p[3]);
            float ps = p[0] + p[1] + p[2] + p[3];
#pragma unroll
            for (int off = 8; off; off >>= 1)
                ps += __shfl_xor_sync(0xffffffffu, ps, off);
            lrow[i] = lrow[i] * corr + ps;
            mrow[i] = mnew;
#pragma unroll
            for (int c = 0; c < 8; c++) o[i][c] *= corr;
        }
        __syncthreads();   // Ps visible to all

        // O += P @ V
#pragma unroll 2
        for (int j = 0; j < 64; j++) {
            float4 v0 = *(const float4*)&Vs[j * 128 + tx * 4];
            float4 v1 = *(const float4*)&Vs[j * 128 + 64 + tx * 4];
#pragma unroll
            for (int i = 0; i < 4; i++) {
                float p = Ps[(ty * 4 + i) * 64 + j];
                o[i][0] += p * v0.x; o[i][1] += p * v0.y;
                o[i][2] += p * v0.z; o[i][3] += p * v0.w;
                o[i][4] += p * v1.x; o[i][5] += p * v1.y;
                o[i][6] += p * v1.z; o[i][7] += p * v1.w;
            }
        }
    }

    // normalize + store: out[s][h*128 + d]
#pragma unroll
    for (int i = 0; i < 4; i++) {
        int s = q0 + ty * 4 + i;
        float inv = 1.0f / lrow[i];
        float* dst = out + (size_t)s * OUT_N + h * HD;
        *(float4*)(dst + tx * 4) =
            make_float4(o[i][0] * inv, o[i][1] * inv, o[i][2] * inv, o[i][3] * inv);
        *(float4*)(dst + 64 + tx * 4) =
            make_float4(o[i][4] * inv, o[i][5] * inv, o[i][6] * inv, o[i][7] * inv);
    }
}

// ---------------------------------------------------------------------------
extern "C" void kernel_launch(void* const* d_in, const int* in_sizes, int n_in,
                              void* d_out, int out_size)
{
    const int*   positions = (const int*)  d_in[0];
    const float* hidden    = (const float*)d_in[1];
    const float* w_qkv     = (const float*)d_in[2];
    const float* b_qkv     = (const float*)d_in[3];
    const float* w_dense   = (const float*)d_in[4];
    const float* b_dense   = (const float*)d_in[5];
    float* out = (float*)d_out;

    float *qkv_p, *att_p;
    cudaGetSymbolAddress((void**)&qkv_p, g_qkv);
    cudaGetSymbolAddress((void**)&att_p, g_att);

    const int ATTN_SMEM = (128 * 64 + 128 * 64 + 64 * 128 + 64 * 64) * 4; // 114688
    cudaFuncSetAttribute(attn_kernel,
                         cudaFuncAttributeMaxDynamicSharedMemorySize, ATTN_SMEM);

    dim3 blk(256);
    // 1) QKV = hidden @ w_qkv^T + b_qkv
    sgemm_bt_bias<<<dim3(QKV_N / 128, S_LEN / 128), blk>>>(
        hidden, w_qkv, b_qkv, qkv_p, S_LEN, QKV_N, HIDDEN);
    // 2) RoPE tables + apply (in-place on q,k slots)
    cs_table_kernel<<<(S_LEN * 64 + 255) / 256, blk>>>(positions);
    rope_apply_kernel<<<(S_LEN * NKV * 5 * 64) / 256, blk>>>();
    // 3) blocksparse attention -> g_att [S][NH*HD]
    attn_kernel<<<dim3(32, 32), blk, ATTN_SMEM>>>(att_p);
    // 4) out = g_att @ w_dense^T + b_dense
    sgemm_bt_bias<<<dim3(OUT_N / 128, S_LEN / 128), blk>>>(
        att_p, w_dense, b_dense, out, S_LEN, OUT_N, HIDDEN);
}

// round 3
// speedup vs baseline: 1.9037x; 1.9037x over previous
#include <cuda_runtime.h>
#include <cstdint>
#include <math.h>

#define S_LEN   2048
#define HIDDEN  4096
#define NHEADS  32
#define NKV     8
#define HD      128
#define QPK     4
#define QKV_N   6144          // NKV*(QPK+2)*HD
#define OUT_N   4096          // NHEADS*HD
#define SCALE_ATT 0.0078125f  // 1/HD

// ---------------- scratch (device globals: no allocations allowed) ----------
__device__ float g_qkv[S_LEN * QKV_N];   // 50 MB
__device__ float g_att[S_LEN * OUT_N];   // 32 MB
__device__ float g_cos[S_LEN * 64];
__device__ float g_sin[S_LEN * 64];

// ---------------- helpers ---------------------------------------------------
__device__ __forceinline__ uint32_t f2tf32(float x) {
    uint32_t u;
    asm("cvt.rna.tf32.f32 %0, %1;" : "=r"(u) : "f"(x));
    return u;
}
// D += A(16x8, row-major) * B(8x8, col-major)  tf32 inputs, f32 accum
__device__ __forceinline__ void mma_16x8x8(float* c, const uint32_t* a,
                                           const uint32_t* b) {
    asm volatile(
        "mma.sync.aligned.m16n8k8.row.col.f32.tf32.tf32.f32 "
        "{%0,%1,%2,%3}, {%4,%5,%6,%7}, {%8,%9}, {%0,%1,%2,%3};\n"
        : "+f"(c[0]), "+f"(c[1]), "+f"(c[2]), "+f"(c[3])
        : "r"(a[0]), "r"(a[1]), "r"(a[2]), "r"(a[3]), "r"(b[0]), "r"(b[1]));
}

// ---------------------------------------------------------------------------
// tf32 mma.sync GEMM: C[M,N] = A[M,K] @ B[N,K]^T + bias[N]  (K-major operands)
// CTA 128x128, BK=32, 8 warps (2x4), warp tile 64x32.
// SMEM rows = 32 floats (128B), 16B-granule XOR swizzle: f4 ^= (row & 7).
// ---------------------------------------------------------------------------
#define BKT 32
__global__ __launch_bounds__(256) void gemm_tf32_mma(
    const float* __restrict__ A, const float* __restrict__ B,
    const float* __restrict__ bias, float* __restrict__ C,
    int N, int K)
{
    __shared__ uint32_t As[128 * 32];
    __shared__ uint32_t Bs[128 * 32];

    const int tid  = threadIdx.x;
    const int wid  = tid >> 5, lane = tid & 31;
    const int gid  = lane >> 2, tig = lane & 3;
    const int wm   = wid >> 2, wn = wid & 3;      // warp grid 2 x 4
    const int m0   = blockIdx.y * 128;
    const int n0   = blockIdx.x * 128;

    const int lr = tid >> 1;           // row this thread loads (0..127)
    const int lf = (tid & 1) * 4;      // starting float4 index (0 or 4)

    const float* Ap = A + (size_t)(m0 + lr) * K + lf * 4;
    const float* Bp = B + (size_t)(n0 + lr) * K + lf * 4;
    const uint32_t swz = (uint32_t)(lr & 7);

    float acc[4][4][4];
#pragma unroll
    for (int mi = 0; mi < 4; mi++)
#pragma unroll
        for (int nj = 0; nj < 4; nj++)
#pragma unroll
            for (int t = 0; t < 4; t++) acc[mi][nj][t] = 0.0f;

    float4 pa[4], pb[4];
    // prologue: tile 0
#pragma unroll
    for (int j = 0; j < 4; j++) {
        pa[j] = *(const float4*)(Ap + j * 4);
        pb[j] = *(const float4*)(Bp + j * 4);
    }
#pragma unroll
    for (int j = 0; j < 4; j++) {
        uint32_t col = (uint32_t)(lf + j) ^ swz;
        *(uint4*)&As[lr * 32 + col * 4] =
            make_uint4(f2tf32(pa[j].x), f2tf32(pa[j].y), f2tf32(pa[j].z), f2tf32(pa[j].w));
        *(uint4*)&Bs[lr * 32 + col * 4] =
            make_uint4(f2tf32(pb[j].x), f2tf32(pb[j].y), f2tf32(pb[j].z), f2tf32(pb[j].w));
    }
    __syncthreads();

    const int KT = K / BKT;
    for (int kt = 0; kt < KT; kt++) {
        if (kt + 1 < KT) {
            const float* Ap2 = Ap + (kt + 1) * BKT;
            const float* Bp2 = Bp + (kt + 1) * BKT;
#pragma unroll
            for (int j = 0; j < 4; j++) {
                pa[j] = *(const float4*)(Ap2 + j * 4);
                pb[j] = *(const float4*)(Bp2 + j * 4);
            }
        }

#pragma unroll
        for (int ks = 0; ks < 4; ks++) {
            const uint32_t fg0 = ks * 2;          // (ks*8) >> 2
            uint32_t a[4][4], b[4][2];
#pragma unroll
            for (int mi = 0; mi < 4; mi++) {
                int r = wm * 64 + mi * 16 + gid;
                uint32_t x0 = (fg0 ^ (uint32_t)(r & 7)) * 4 + tig;
                uint32_t x1 = ((fg0 + 1) ^ (uint32_t)(r & 7)) * 4 + tig;
                a[mi][0] = As[r * 32 + x0];
                a[mi][1] = As[(r + 8) * 32 + x0];
                a[mi][2] = As[r * 32 + x1];
                a[mi][3] = As[(r + 8) * 32 + x1];
            }
#pragma unroll
            for (int nj = 0; nj < 4; nj++) {
                int r = wn * 32 + nj * 8 + gid;
                uint32_t x0 = (fg0 ^ (uint32_t)(r & 7)) * 4 + tig;
                uint32_t x1 = ((fg0 + 1) ^ (uint32_t)(r & 7)) * 4 + tig;
                b[nj][0] = Bs[r * 32 + x0];
                b[nj][1] = Bs[r * 32 + x1];
            }
#pragma unroll
            for (int mi = 0; mi < 4; mi++)
#pragma unroll
                for (int nj = 0; nj < 4; nj++)
                    mma_16x8x8(acc[mi][nj], a[mi], b[nj]);
        }

        __syncthreads();
        if (kt + 1 < KT) {
#pragma unroll
            for (int j = 0; j < 4; j++) {
                uint32_t col = (uint32_t)(lf + j) ^ swz;
                *(uint4*)&As[lr * 32 + col * 4] =
                    make_uint4(f2tf32(pa[j].x), f2tf32(pa[j].y), f2tf32(pa[j].z), f2tf32(pa[j].w));
                *(uint4*)&Bs[lr * 32 + col * 4] =
                    make_uint4(f2tf32(pb[j].x), f2tf32(pb[j].y), f2tf32(pb[j].z), f2tf32(pb[j].w));
            }
            __syncthreads();
        }
    }

    // epilogue: c0,c1 -> (row, 2*tig..+1), c2,c3 -> (row+8, same cols)
    const float* bp = bias + n0 + wn * 32;
#pragma unroll
    for (int nj = 0; nj < 4; nj++) {
        int c = nj * 8 + 2 * tig;
        float2 bb = *(const float2*)(bp + c);
#pragma unroll
        for (int mi = 0; mi < 4; mi++) {
            int r = m0 + wm * 64 + mi * 16 + gid;
            float* dst = C + (size_t)r * N + n0 + wn * 32 + c;
            *(float2*)dst = make_float2(acc[mi][nj][0] + bb.x, acc[mi][nj][1] + bb.y);
            *(float2*)(dst + 8 * N) =
                make_float2(acc[mi][nj][2] + bb.x, acc[mi][nj][3] + bb.y);
        }
    }
}

// ---------------------------------------------------------------------------
// RoPE tables: cos/sin of fp32(pos * fp32(inv_freq)) via fp64 trig.
// ---------------------------------------------------------------------------
__global__ void cs_table_kernel(const int* __restrict__ positions)
{
    int idx = blockIdx.x * blockDim.x + threadIdx.x;
    if (idx >= S_LEN * 64) return;
    int i = idx & 63;
    int s = idx >> 6;
    float pos = (float)positions[s];
    double e = (double)(2 * i) / 128.0;
    float invf = (float)(1.0 / pow(1.0e6, e));
    float freq = pos * invf;
    g_cos[idx] = (float)cos((double)freq);
    g_sin[idx] = (float)sin((double)freq);
}

__global__ void rope_apply_kernel()
{
    int idx = blockIdx.x * blockDim.x + threadIdx.x;
    int i = idx & 63;
    int t = idx >> 6;
    int slot = t % 5;
    t /= 5;
    int kvh = t & 7;
    int s = t >> 3;
    float c  = g_cos[(s << 6) | i];
    float sn = g_sin[(s << 6) | i];
    size_t base = (size_t)s * QKV_N + kvh * 768 + slot * 128 + i;
    float x1 = g_qkv[base];
    float x2 = g_qkv[base + 64];
    g_qkv[base]      = x1 * c - x2 * sn;
    g_qkv[base + 64] = x2 * c + x1 * sn;
}

// ---------------------------------------------------------------------------
// Blocksparse flash attention (round-1 version; 875us, FMA-bound).
// ---------------------------------------------------------------------------
__global__ __launch_bounds__(256) void attn_kernel(float* __restrict__ out)
{
    extern __shared__ float sm[];
    float* Qt = sm;
    float* Kt = Qt + 128 * 64;
    float* Vs = Kt + 128 * 64;
    float* Ps = Vs + 64 * 128;

    const int qb = blockIdx.x;
    const int h  = blockIdx.y;
    const int kvh = h >> 2, slot = h & 3;
    const int tid = threadIdx.x;
    const int tx = tid & 15;
    const int ty = tid >> 4;
    const int q0 = qb * 64;
    const int lr  = tid >> 2;
    const int lf0 = tid & 3;

    const size_t qoff = (size_t)kvh * 768 + slot * 128;
    const size_t koff = (size_t)kvh * 768 + 512;
    const size_t voff = (size_t)kvh * 768 + 640;

#pragma unroll
    for (int it = 0; it < 8; it++) {
        int f = lf0 + it * 4;
        float4 v = *(const float4*)(g_qkv + (size_t)(q0 + lr) * QKV_N + qoff + f * 4);
        Qt[(f * 4 + 0) * 64 + lr] = v.x;
        Qt[(f * 4 + 1) * 64 + lr] = v.y;
        Qt[(f * 4 + 2) * 64 + lr] = v.z;
        Qt[(f * 4 + 3) * 64 + lr] = v.w;
    }

    float o[4][8];
#pragma unroll
    for (int i = 0; i < 4; i++)
#pragma unroll
        for (int c = 0; c < 8; c++) o[i][c] = 0.0f;
    float mrow[4] = {-1e30f, -1e30f, -1e30f, -1e30f};
    float lrow[4] = {0.0f, 0.0f, 0.0f, 0.0f};

    for (int kb = 0; kb <= qb; kb++) {
        bool allowed = ((qb - kb) < 16) || (((kb + h + 1) & 7) == 0);
        if (!allowed) continue;
        __syncthreads();
        int k0 = kb * 64;
#pragma unroll
        for (int it = 0; it < 8; it++) {
            int f = lf0 + it * 4;
            float4 v = *(const float4*)(g_qkv + (size_t)(k0 + lr) * QKV_N + koff + f * 4);
            Kt[(f * 4 + 0) * 64 + lr] = v.x;
            Kt[(f * 4 + 1) * 64 + lr] = v.y;
            Kt[(f * 4 + 2) * 64 + lr] = v.z;
            Kt[(f * 4 + 3) * 64 + lr] = v.w;
        }
#pragma unroll
        for (int it = 0; it < 8; it++) {
            int idx = tid + it * 256;
            int r = idx >> 5, f = idx & 31;
            *(float4*)(Vs + r * 128 + f * 4) =
                *(const float4*)(g_qkv + (size_t)(k0 + r) * QKV_N + voff + f * 4);
        }
        __syncthreads();

        float s_acc[4][4];
#pragma unroll
        for (int i = 0; i < 4; i++)
#pragma unroll
            for (int j = 0; j < 4; j++) s_acc[i][j] = 0.0f;
#pragma unroll 4
        for (int d = 0; d < 128; d++) {
            float4 a = *(const float4*)&Qt[d * 64 + ty * 4];
            float4 b = *(const float4*)&Kt[d * 64 + tx * 4];
            float av[4] = {a.x, a.y, a.z, a.w};
            float bv[4] = {b.x, b.y, b.z, b.w};
#pragma unroll
            for (int i = 0; i < 4; i++)
#pragma unroll
                for (int j = 0; j < 4; j++) s_acc[i][j] += av[i] * bv[j];
        }

        const bool diag = (kb == qb);
#pragma unroll
        for (int i = 0; i < 4; i++) {
            int r = ty * 4 + i;
            float sv[4];
#pragma unroll
            for (int j = 0; j < 4; j++) {
                int c = tx * 4 + j;
                float v = s_acc[i][j] * SCALE_ATT;
                if (diag && c > r) v = -1e30f;
                sv[j] = v;
            }
            float mb = fmaxf(fmaxf(sv[0], sv[1]), fmaxf(sv[2], sv[3]));
#pragma unroll
            for (int off = 8; off; off >>= 1)
                mb = fmaxf(mb, __shfl_xor_sync(0xffffffffu, mb, off));
            float mnew = fmaxf(mrow[i], mb);
            float corr = __expf(mrow[i] - mnew);
            float p[4];
#pragma unroll
            for (int j = 0; j < 4; j++) p[j] = __expf(sv[j] - mnew);
            *(float4*)&Ps[r * 64 + tx * 4] = make_float4(p[0], p[1], p[2], p[3]);
            float ps = p[0] + p[1] + p[2] + p[3];
#pragma unroll
            for (int off = 8; off; off >>= 1)
                ps += __shfl_xor_sync(0xffffffffu, ps, off);
            lrow[i] = lrow[i] * corr + ps;
            mrow[i] = mnew;
#pragma unroll
            for (int c = 0; c < 8; c++) o[i][c] *= corr;
        }
        __syncthreads();

#pragma unroll 2
        for (int j = 0; j < 64; j++) {
            float4 v0 = *(const float4*)&Vs[j * 128 + tx * 4];
            float4 v1 = *(const float4*)&Vs[j * 128 + 64 + tx * 4];
#pragma unroll
            for (int i = 0; i < 4; i++) {
                float p = Ps[(ty * 4 + i) * 64 + j];
                o[i][0] += p * v0.x; o[i][1] += p * v0.y;
                o[i][2] += p * v0.z; o[i][3] += p * v0.w;
                o[i][4] += p * v1.x; o[i][5] += p * v1.y;
                o[i][6] += p * v1.z; o[i][7] += p * v1.w;
            }
        }
    }

#pragma unroll
    for (int i = 0; i < 4; i++) {
        int s = q0 + ty * 4 + i;
        float inv = 1.0f / lrow[i];
        float* dst = out + (size_t)s * OUT_N + h * HD;
        *(float4*)(dst + tx * 4) =
            make_float4(o[i][0] * inv, o[i][1] * inv, o[i][2] * inv, o[i][3] * inv);
        *(float4*)(dst + 64 + tx * 4) =
            make_float4(o[i][4] * inv, o[i][5] * inv, o[i][6] * inv, o[i][7] * inv);
    }
}

// ---------------------------------------------------------------------------
extern "C" void kernel_launch(void* const* d_in, const int* in_sizes, int n_in,
                              void* d_out, int out_size)
{
    const int*   positions = (const int*)  d_in[0];
    const float* hidden    = (const float*)d_in[1];
    const float* w_qkv     = (const float*)d_in[2];
    const float* b_qkv     = (const float*)d_in[3];
    const float* w_dense   = (const float*)d_in[4];
    const float* b_dense   = (const float*)d_in[5];
    float* out = (float*)d_out;

    float *qkv_p, *att_p;
    cudaGetSymbolAddress((void**)&qkv_p, g_qkv);
    cudaGetSymbolAddress((void**)&att_p, g_att);

    const int ATTN_SMEM = (128 * 64 + 128 * 64 + 64 * 128 + 64 * 64) * 4; // 114688
    cudaFuncSetAttribute(attn_kernel,
                         cudaFuncAttributeMaxDynamicSharedMemorySize, ATTN_SMEM);

    dim3 blk(256);
    // 1) QKV = hidden @ w_qkv^T + b_qkv   (tf32 mma.sync)
    gemm_tf32_mma<<<dim3(QKV_N / 128, S_LEN / 128), blk>>>(
        hidden, w_qkv, b_qkv, qkv_p, QKV_N, HIDDEN);
    // 2) RoPE tables + apply
    cs_table_kernel<<<(S_LEN * 64 + 255) / 256, blk>>>(positions);
    rope_apply_kernel<<<(S_LEN * NKV * 5 * 64) / 256, blk>>>();
    // 3) blocksparse attention
    attn_kernel<<<dim3(32, 32), blk, ATTN_SMEM>>>(att_p);
    // 4) out = g_att @ w_dense^T + b_dense   (tf32 mma.sync)
    gemm_tf32_mma<<<dim3(OUT_N / 128, S_LEN / 128), blk>>>(
        att_p, w_dense, b_dense, out, OUT_N, HIDDEN);
}

// round 4
// speedup vs baseline: 1.9430x; 1.0206x over previous
#include <cuda_runtime.h>
#include <cstdint>
#include <math.h>

#define S_LEN   2048
#define HIDDEN  4096
#define NHEADS  32
#define NKV     8
#define HD      128
#define QPK     4
#define QKV_N   6144          // NKV*(QPK+2)*HD
#define OUT_N   4096          // NHEADS*HD
#define SCALE_ATT 0.0078125f  // 1/HD

// ---------------- scratch (device globals: no allocations allowed) ----------
__device__ float g_qkv[S_LEN * QKV_N];   // 50 MB
__device__ float g_att[S_LEN * OUT_N];   // 32 MB
__device__ float g_cos[S_LEN * 64];
__device__ float g_sin[S_LEN * 64];

// ---------------- helpers ---------------------------------------------------
__device__ __forceinline__ uint32_t smem_u32(const void* p) {
    uint32_t a;
    asm("{ .reg .u64 t; cvta.to.shared.u64 t, %1; cvt.u32.u64 %0, t; }"
        : "=r"(a) : "l"(p));
    return a;
}
__device__ __forceinline__ uint32_t f2tf32(float x) {
    uint32_t u;
    asm("cvt.rna.tf32.f32 %0, %1;" : "=r"(u) : "f"(x));
    return u;
}
// D += A(16x8, row-major) * B(8x8, col-major)  tf32 inputs, f32 accum
__device__ __forceinline__ void mma_16x8x8(float* c, const uint32_t* a,
                                           const uint32_t* b) {
    asm volatile(
        "mma.sync.aligned.m16n8k8.row.col.f32.tf32.tf32.f32 "
        "{%0,%1,%2,%3}, {%4,%5,%6,%7}, {%8,%9}, {%0,%1,%2,%3};\n"
        : "+f"(c[0]), "+f"(c[1]), "+f"(c[2]), "+f"(c[3])
        : "r"(a[0]), "r"(a[1]), "r"(a[2]), "r"(a[3]), "r"(b[0]), "r"(b[1]));
}
// 16x8 b32 tile via four 8x8 b16 matrices. Thread t's reg in each sub-tile is
// b32 element (t/4, t%4). Sub-tiles: r0=(rows0-7,c0-3) r1=(rows0-7,c4-7)
// r2=(rows8-15,c0-3) r3=(rows8-15,c4-7).
__device__ __forceinline__ void ldsm4(uint32_t addr, uint32_t& r0, uint32_t& r1,
                                      uint32_t& r2, uint32_t& r3) {
    asm volatile("ldmatrix.sync.aligned.m8n8.x4.shared.b16 {%0,%1,%2,%3}, [%4];"
                 : "=r"(r0), "=r"(r1), "=r"(r2), "=r"(r3) : "r"(addr));
}

// ---------------------------------------------------------------------------
// tf32 mma.sync GEMM: C[M,N] = A[M,K] @ B[N,K]^T + bias[N]  (K-major operands)
// CTA 128x128, BK=32, 8 warps (2x4), warp tile 64x32. ldmatrix fragment loads.
// SMEM rows = 32 floats (128B), 16B-granule XOR swizzle: chunk ^= (row & 7).
// ---------------------------------------------------------------------------
#define BKT 32
__global__ __launch_bounds__(256) void gemm_tf32_mma(
    const float* __restrict__ A, const float* __restrict__ B,
    const float* __restrict__ bias, float* __restrict__ C,
    int N, int K)
{
    __shared__ uint32_t As[128 * 32];
    __shared__ uint32_t Bs[128 * 32];

    const int tid  = threadIdx.x;
    const int wid  = tid >> 5, lane = tid & 31;
    const int gid  = lane >> 2, tig = lane & 3;
    const int wm   = wid >> 2, wn = wid & 3;      // warp grid 2 x 4
    const int m0   = blockIdx.y * 128;
    const int n0   = blockIdx.x * 128;

    // ldmatrix per-thread address components
    const int rowb = (lane & 7) + ((lane >> 4) << 3);   // local row in 16-row tile
    const uint32_t swz7 = (uint32_t)(rowb & 7);
    const uint32_t chp  = (uint32_t)((lane >> 3) & 1);  // chunk parity (cols 0-3 / 4-7)
    const uint32_t asb = smem_u32(As);
    const uint32_t bsb = smem_u32(Bs);

    const int lr = tid >> 1;           // row this thread loads (0..127)
    const int lf = (tid & 1) * 4;      // starting float4 index (0 or 4)

    const float* Ap = A + (size_t)(m0 + lr) * K + lf * 4;
    const float* Bp = B + (size_t)(n0 + lr) * K + lf * 4;
    const uint32_t swz = (uint32_t)(lr & 7);

    float acc[4][4][4];
#pragma unroll
    for (int mi = 0; mi < 4; mi++)
#pragma unroll
        for (int nj = 0; nj < 4; nj++)
#pragma unroll
            for (int t = 0; t < 4; t++) acc[mi][nj][t] = 0.0f;

    float4 pa[4], pb[4];
#pragma unroll
    for (int j = 0; j < 4; j++) {
        pa[j] = *(const float4*)(Ap + j * 4);
        pb[j] = *(const float4*)(Bp + j * 4);
    }
#pragma unroll
    for (int j = 0; j < 4; j++) {
        uint32_t col = (uint32_t)(lf + j) ^ swz;
        *(uint4*)&As[lr * 32 + col * 4] =
            make_uint4(f2tf32(pa[j].x), f2tf32(pa[j].y), f2tf32(pa[j].z), f2tf32(pa[j].w));
        *(uint4*)&Bs[lr * 32 + col * 4] =
            make_uint4(f2tf32(pb[j].x), f2tf32(pb[j].y), f2tf32(pb[j].z), f2tf32(pb[j].w));
    }
    __syncthreads();

    const int KT = K / BKT;
    for (int kt = 0; kt < KT; kt++) {
        if (kt + 1 < KT) {
            const float* Ap2 = Ap + (kt + 1) * BKT;
            const float* Bp2 = Bp + (kt + 1) * BKT;
#pragma unroll
            for (int j = 0; j < 4; j++) {
                pa[j] = *(const float4*)(Ap2 + j * 4);
                pb[j] = *(const float4*)(Bp2 + j * 4);
            }
        }

#pragma unroll
        for (int ks = 0; ks < 4; ks++) {
            const uint32_t lo = (((2u * ks + chp) ^ swz7) << 4);
            uint32_t a[4][4], b[4][2];
#pragma unroll
            for (int mi = 0; mi < 4; mi++) {
                uint32_t r0, r1, r2, r3;
                ldsm4(asb + (uint32_t)(wm * 64 + mi * 16 + rowb) * 128 + lo,
                      r0, r1, r2, r3);
                a[mi][0] = r0; a[mi][1] = r2; a[mi][2] = r1; a[mi][3] = r3;
            }
#pragma unroll
            for (int njp = 0; njp < 2; njp++) {
                uint32_t r0, r1, r2, r3;
                ldsm4(bsb + (uint32_t)(wn * 32 + njp * 16 + rowb) * 128 + lo,
                      r0, r1, r2, r3);
                b[2 * njp][0] = r0;     b[2 * njp][1] = r1;
                b[2 * njp + 1][0] = r2; b[2 * njp + 1][1] = r3;
            }
#pragma unroll
            for (int mi = 0; mi < 4; mi++)
#pragma unroll
                for (int nj = 0; nj < 4; nj++)
                    mma_16x8x8(acc[mi][nj], a[mi], b[nj]);
        }

        __syncthreads();
        if (kt + 1 < KT) {
#pragma unroll
            for (int j = 0; j < 4; j++) {
                uint32_t col = (uint32_t)(lf + j) ^ swz;
                *(uint4*)&As[lr * 32 + col * 4] =
                    make_uint4(f2tf32(pa[j].x), f2tf32(pa[j].y), f2tf32(pa[j].z), f2tf32(pa[j].w));
                *(uint4*)&Bs[lr * 32 + col * 4] =
                    make_uint4(f2tf32(pb[j].x), f2tf32(pb[j].y), f2tf32(pb[j].z), f2tf32(pb[j].w));
            }
            __syncthreads();
        }
    }

    const float* bp = bias + n0 + wn * 32;
#pragma unroll
    for (int nj = 0; nj < 4; nj++) {
        int c = nj * 8 + 2 * tig;
        float2 bb = *(const float2*)(bp + c);
#pragma unroll
        for (int mi = 0; mi < 4; mi++) {
            int r = m0 + wm * 64 + mi * 16 + gid;
            float* dst = C + (size_t)r * N + n0 + wn * 32 + c;
            *(float2*)dst = make_float2(acc[mi][nj][0] + bb.x, acc[mi][nj][1] + bb.y);
            *(float2*)(dst + 8 * N) =
                make_float2(acc[mi][nj][2] + bb.x, acc[mi][nj][3] + bb.y);
        }
    }
}

// ---------------------------------------------------------------------------
// RoPE tables + apply (unchanged).
// ---------------------------------------------------------------------------
__global__ void cs_table_kernel(const int* __restrict__ positions)
{
    int idx = blockIdx.x * blockDim.x + threadIdx.x;
    if (idx >= S_LEN * 64) return;
    int i = idx & 63;
    int s = idx >> 6;
    float pos = (float)positions[s];
    double e = (double)(2 * i) / 128.0;
    float invf = (float)(1.0 / pow(1.0e6, e));
    float freq = pos * invf;
    g_cos[idx] = (float)cos((double)freq);
    g_sin[idx] = (float)sin((double)freq);
}

__global__ void rope_apply_kernel()
{
    int idx = blockIdx.x * blockDim.x + threadIdx.x;
    int i = idx & 63;
    int t = idx >> 6;
    int slot = t % 5;
    t /= 5;
    int kvh = t & 7;
    int s = t >> 3;
    float c  = g_cos[(s << 6) | i];
    float sn = g_sin[(s << 6) | i];
    size_t base = (size_t)s * QKV_N + kvh * 768 + slot * 128 + i;
    float x1 = g_qkv[base];
    float x2 = g_qkv[base + 64];
    g_qkv[base]      = x1 * c - x2 * sn;
    g_qkv[base + 64] = x2 * c + x1 * sn;
}

// ---------------------------------------------------------------------------
// Tensor-core blocksparse flash attention.
// CTA = (q-block 64, head), 128 threads = 4 warps, warp = 16 q-rows.
// smem: Qs[64][128] / Ks[64][128] (512B rows), Vt[128][64] (transposed, 256B
// rows), Ps[64][64]. All tf32 with 16B-chunk XOR-(row&7) swizzle per 128B
// sub-row. S held in accum regs (warp owns full rows -> shfl-only softmax).
// ---------------------------------------------------------------------------
#define ATT_QS 0
#define ATT_KS 32768
#define ATT_VT 65536
#define ATT_PS 98304
#define ATT_SMEM 114688

__global__ __launch_bounds__(128) void attn_tc_kernel(float* __restrict__ out)
{
    extern __shared__ char smem[];
    const uint32_t sb = smem_u32(smem);
    const int tid = threadIdx.x, lane = tid & 31, w = tid >> 5;
    const int gid = lane >> 2, tig = lane & 3;
    const int qb = blockIdx.x, h = blockIdx.y;
    const int kvh = h >> 2, slot = h & 3;
    const int q0 = qb * 64;
    const size_t qoff = (size_t)kvh * 768 + slot * 128;
    const size_t koff = (size_t)kvh * 768 + 512;
    const size_t voff = (size_t)kvh * 768 + 640;

    const int rowb = (lane & 7) + ((lane >> 4) << 3);
    const uint32_t swz7 = (uint32_t)(rowb & 7);
    const uint32_t chp  = (uint32_t)((lane >> 3) & 1);
    const int Rw = w * 16;

    // ---- load Q tile (tf32, swizzled) ----
#pragma unroll
    for (int i = 0; i < 16; i++) {
        int idx = tid + i * 128;
        int r = idx >> 5, c = idx & 31;
        float4 v = *(const float4*)(g_qkv + (size_t)(q0 + r) * QKV_N + qoff + c * 4);
        uint32_t off = (uint32_t)r * 512 + ((uint32_t)(c >> 3) << 7)
                     + ((((uint32_t)(c & 7)) ^ (uint32_t)(r & 7)) << 4);
        *(uint4*)(smem + ATT_QS + off) =
            make_uint4(f2tf32(v.x), f2tf32(v.y), f2tf32(v.z), f2tf32(v.w));
    }

    float Oa[16][4];
#pragma unroll
    for (int nf = 0; nf < 16; nf++)
#pragma unroll
        for (int t = 0; t < 4; t++) Oa[nf][t] = 0.0f;
    float m0r = -1e30f, m1r = -1e30f, l0 = 0.0f, l1 = 0.0f;

    for (int kb = 0; kb <= qb; kb++) {
        if (!(((qb - kb) < 16) || (((kb + h + 1) & 7) == 0))) continue;
        const int k0 = kb * 64;
        __syncthreads();
        // K tile
#pragma unroll
        for (int i = 0; i < 16; i++) {
            int idx = tid + i * 128;
            int r = idx >> 5, c = idx & 31;
            float4 v = *(const float4*)(g_qkv + (size_t)(k0 + r) * QKV_N + koff + c * 4);
            uint32_t off = (uint32_t)r * 512 + ((uint32_t)(c >> 3) << 7)
                         + ((((uint32_t)(c & 7)) ^ (uint32_t)(r & 7)) << 4);
            *(uint4*)(smem + ATT_KS + off) =
                make_uint4(f2tf32(v.x), f2tf32(v.y), f2tf32(v.z), f2tf32(v.w));
        }
        // V tile, transposed to [d][key]
#pragma unroll
        for (int i = 0; i < 16; i++) {
            int idx = tid + i * 128;
            int r = idx & 63, c = idx >> 6;
            float4 v = *(const float4*)(g_qkv + (size_t)(k0 + r) * QKV_N + voff + c * 4);
            uint32_t vv[4] = {f2tf32(v.x), f2tf32(v.y), f2tf32(v.z), f2tf32(v.w)};
#pragma unroll
            for (int j = 0; j < 4; j++) {
                int d = 4 * c + j;
                uint32_t off = (uint32_t)d * 256 + (((uint32_t)r >> 5) << 7)
                    + (((((uint32_t)r >> 2) & 7) ^ (uint32_t)(d & 7)) << 4)
                    + (uint32_t)(r & 3) * 4;
                *(uint32_t*)(smem + ATT_VT + off) = vv[j];
            }
        }
        __syncthreads();

        // ---- S = Q @ K^T ----
        float Sa[8][4];
#pragma unroll
        for (int nj = 0; nj < 8; nj++)
#pragma unroll
            for (int t = 0; t < 4; t++) Sa[nj][t] = 0.0f;
#pragma unroll
        for (int ks2 = 0; ks2 < 16; ks2++) {
            uint32_t ch = 2u * ks2 + chp;
            uint32_t hi = (ch >> 3) << 7, lo = ((ch & 7) ^ swz7) << 4;
            uint32_t r0, r1, r2, r3;
            ldsm4(sb + ATT_QS + (uint32_t)(Rw + rowb) * 512 + hi + lo, r0, r1, r2, r3);
            uint32_t Af[4] = {r0, r2, r1, r3};
#pragma unroll
            for (int njp = 0; njp < 4; njp++) {
                uint32_t b0, b1, b2, b3;
                ldsm4(sb + ATT_KS + (uint32_t)(njp * 16 + rowb) * 512 + hi + lo,
                      b0, b1, b2, b3);
                uint32_t B0[2] = {b0, b1}, B1[2] = {b2, b3};
                mma_16x8x8(Sa[2 * njp], Af, B0);
                mma_16x8x8(Sa[2 * njp + 1], Af, B1);
            }
        }

        // ---- softmax (rows r0l = Rw+gid, r1l = +8; block-local coords) ----
        const bool diag = (kb == qb);
        const int r0l = Rw + gid, r1l = r0l + 8;
        float mx0 = -1e30f, mx1 = -1e30f;
#pragma unroll
        for (int nj = 0; nj < 8; nj++) {
            int c0 = nj * 8 + 2 * tig;
            float v0 = Sa[nj][0] * SCALE_ATT;
            float v1 = Sa[nj][1] * SCALE_ATT;
            float v2 = Sa[nj][2] * SCALE_ATT;
            float v3 = Sa[nj][3] * SCALE_ATT;
            if (diag) {
                if (c0 > r0l)     v0 = -1e30f;
                if (c0 + 1 > r0l) v1 = -1e30f;
                if (c0 > r1l)     v2 = -1e30f;
                if (c0 + 1 > r1l) v3 = -1e30f;
            }
            Sa[nj][0] = v0; Sa[nj][1] = v1; Sa[nj][2] = v2; Sa[nj][3] = v3;
            mx0 = fmaxf(mx0, fmaxf(v0, v1));
            mx1 = fmaxf(mx1, fmaxf(v2, v3));
        }
        mx0 = fmaxf(mx0, __shfl_xor_sync(0xffffffffu, mx0, 1));
        mx0 = fmaxf(mx0, __shfl_xor_sync(0xffffffffu, mx0, 2));
        mx1 = fmaxf(mx1, __shfl_xor_sync(0xffffffffu, mx1, 1));
        mx1 = fmaxf(mx1, __shfl_xor_sync(0xffffffffu, mx1, 2));
        const float mn0 = fmaxf(m0r, mx0), mn1 = fmaxf(m1r, mx1);
        const float corr0 = __expf(m0r - mn0), corr1 = __expf(m1r - mn1);
        float s0 = 0.0f, s1 = 0.0f;
#pragma unroll
        for (int nj = 0; nj < 8; nj++) {
            float p0 = __expf(Sa[nj][0] - mn0);
            float p1 = __expf(Sa[nj][1] - mn0);
            float p2 = __expf(Sa[nj][2] - mn1);
            float p3 = __expf(Sa[nj][3] - mn1);
            s0 += p0 + p1; s1 += p2 + p3;
            int col = nj * 8 + 2 * tig;
            uint32_t ch = (uint32_t)col >> 2;
            uint32_t base = ((ch >> 3) << 7) + (((ch & 7) ^ (uint32_t)(r0l & 7)) << 4)
                          + ((uint32_t)col & 3) * 4;
            *(uint2*)(smem + ATT_PS + (uint32_t)r0l * 256 + base) =
                make_uint2(f2tf32(p0), f2tf32(p1));
            *(uint2*)(smem + ATT_PS + (uint32_t)r1l * 256 + base) =
                make_uint2(f2tf32(p2), f2tf32(p3));
        }
        s0 += __shfl_xor_sync(0xffffffffu, s0, 1);
        s0 += __shfl_xor_sync(0xffffffffu, s0, 2);
        s1 += __shfl_xor_sync(0xffffffffu, s1, 1);
        s1 += __shfl_xor_sync(0xffffffffu, s1, 2);
        l0 = l0 * corr0 + s0; l1 = l1 * corr1 + s1;
        m0r = mn0; m1r = mn1;
#pragma unroll
        for (int nf = 0; nf < 16; nf++) {
            Oa[nf][0] *= corr0; Oa[nf][1] *= corr0;
            Oa[nf][2] *= corr1; Oa[nf][3] *= corr1;
        }
        __syncwarp();

        // ---- O += P @ V ----
#pragma unroll
        for (int kss = 0; kss < 8; kss++) {
            uint32_t ch = 2u * kss + chp;
            uint32_t hi = (ch >> 3) << 7, lo = ((ch & 7) ^ swz7) << 4;
            uint32_t r0, r1, r2, r3;
            ldsm4(sb + ATT_PS + (uint32_t)(Rw + rowb) * 256 + hi + lo, r0, r1, r2, r3);
            uint32_t Af[4] = {r0, r2, r1, r3};
#pragma unroll
            for (int nfp = 0; nfp < 8; nfp++) {
                uint32_t b0, b1, b2, b3;
                ldsm4(sb + ATT_VT + (uint32_t)(nfp * 16 + rowb) * 256 + hi + lo,
                      b0, b1, b2, b3);
                uint32_t B0[2] = {b0, b1}, B1[2] = {b2, b3};
                mma_16x8x8(Oa[2 * nfp], Af, B0);
                mma_16x8x8(Oa[2 * nfp + 1], Af, B1);
            }
        }
        __syncwarp();
    }

    // ---- epilogue ----
    const float i0 = 1.0f / l0, i1 = 1.0f / l1;
    const int gr0 = q0 + Rw + gid;
    float* d0 = out + (size_t)gr0 * OUT_N + h * HD;
    float* d1 = d0 + (size_t)8 * OUT_N;
#pragma unroll
    for (int nf = 0; nf < 16; nf++) {
        int c = nf * 8 + 2 * tig;
        *(float2*)(d0 + c) = make_float2(Oa[nf][0] * i0, Oa[nf][1] * i0);
        *(float2*)(d1 + c) = make_float2(Oa[nf][2] * i1, Oa[nf][3] * i1);
    }
}

// ---------------------------------------------------------------------------
extern "C" void kernel_launch(void* const* d_in, const int* in_sizes, int n_in,
                              void* d_out, int out_size)
{
    const int*   positions = (const int*)  d_in[0];
    const float* hidden    = (const float*)d_in[1];
    const float* w_qkv     = (const float*)d_in[2];
    const float* b_qkv     = (const float*)d_in[3];
    const float* w_dense   = (const float*)d_in[4];
    const float* b_dense   = (const float*)d_in[5];
    float* out = (float*)d_out;

    float *qkv_p, *att_p;
    cudaGetSymbolAddress((void**)&qkv_p, g_qkv);
    cudaGetSymbolAddress((void**)&att_p, g_att);

    cudaFuncSetAttribute(attn_tc_kernel,
                         cudaFuncAttributeMaxDynamicSharedMemorySize, ATT_SMEM);

    // 1) QKV = hidden @ w_qkv^T + b_qkv   (tf32 mma.sync + ldmatrix)
    gemm_tf32_mma<<<dim3(QKV_N / 128, S_LEN / 128), 256>>>(
        hidden, w_qkv, b_qkv, qkv_p, QKV_N, HIDDEN);
    // 2) RoPE tables + apply
    cs_table_kernel<<<(S_LEN * 64 + 255) / 256, 256>>>(positions);
    rope_apply_kernel<<<(S_LEN * NKV * 5 * 64) / 256, 256>>>();
    // 3) blocksparse attention (tensor cores)
    attn_tc_kernel<<<dim3(32, 32), 128, ATT_SMEM>>>(att_p);
    // 4) out = g_att @ w_dense^T + b_dense
    gemm_tf32_mma<<<dim3(OUT_N / 128, S_LEN / 128), 256>>>(
        att_p, w_dense, b_dense, out, OUT_N, HIDDEN);
}

// round 5
// speedup vs baseline: 3.3166x; 1.7070x over previous
#include <cuda_runtime.h>
#include <cstdint>
#include <math.h>

#define S_LEN   2048
#define HIDDEN  4096
#define NHEADS  32
#define NKV     8
#define HD      128
#define QPK     4
#define QKV_N   6144          // NKV*(QPK+2)*HD
#define OUT_N   4096          // NHEADS*HD
#define SCALE_ATT 0.0078125f  // 1/HD

// ---------------- scratch (device globals: no allocations allowed) ----------
__device__ float g_qkv[S_LEN * QKV_N];        // 50 MB
__device__ float g_att[S_LEN * OUT_N];        // 32 MB
__device__ float g_cos[S_LEN * 64];
__device__ float g_sin[S_LEN * 64];
__device__ float g_hid_t[S_LEN * HIDDEN];     // 32 MB  (tf32-rounded hidden)
__device__ float g_wqkv_t[QKV_N * HIDDEN];    // 100 MB (tf32-rounded w_qkv)
__device__ float g_wd_t[HIDDEN * HIDDEN];     // 64 MB  (tf32-rounded w_dense)

// ---------------- helpers ---------------------------------------------------
__device__ __forceinline__ uint32_t smem_u32(const void* p) {
    uint32_t a;
    asm("{ .reg .u64 t; cvta.to.shared.u64 t, %1; cvt.u32.u64 %0, t; }"
        : "=r"(a) : "l"(p));
    return a;
}
__device__ __forceinline__ uint32_t f2tf32(float x) {
    uint32_t u;
    asm("cvt.rna.tf32.f32 %0, %1;" : "=r"(u) : "f"(x));
    return u;
}
__device__ __forceinline__ void mma_16x8x8(float* c, const uint32_t* a,
                                           const uint32_t* b) {
    asm volatile(
        "mma.sync.aligned.m16n8k8.row.col.f32.tf32.tf32.f32 "
        "{%0,%1,%2,%3}, {%4,%5,%6,%7}, {%8,%9}, {%0,%1,%2,%3};\n"
        : "+f"(c[0]), "+f"(c[1]), "+f"(c[2]), "+f"(c[3])
        : "r"(a[0]), "r"(a[1]), "r"(a[2]), "r"(a[3]), "r"(b[0]), "r"(b[1]));
}
// 16x8 b32 tile via four 8x8 b16 matrices (b32 elem (t/4, t%4) per sub-tile).
__device__ __forceinline__ void ldsm4(uint32_t addr, uint32_t& r0, uint32_t& r1,
                                      uint32_t& r2, uint32_t& r3) {
    asm volatile("ldmatrix.sync.aligned.m8n8.x4.shared.b16 {%0,%1,%2,%3}, [%4];"
                 : "=r"(r0), "=r"(r1), "=r"(r2), "=r"(r3) : "r"(addr));
}
__device__ __forceinline__ void cpa16(uint32_t dst, const void* src) {
    asm volatile("cp.async.cg.shared.global [%0], [%1], 16;" :: "r"(dst), "l"(src));
}
__device__ __forceinline__ void cpa_commit() {
    asm volatile("cp.async.commit_group;" ::: "memory");
}
template <int N>
__device__ __forceinline__ void cpa_wait() {
    asm volatile("cp.async.wait_group %0;" :: "n"(N) : "memory");
}

// ---------------------------------------------------------------------------
// tf32-rounding prep pass (operands pre-rounded so GEMM needs no conversion;
// cvt.rna is idempotent so numerics match converting inside the GEMM).
// ---------------------------------------------------------------------------
__global__ void round_tf32_kernel(const float4* __restrict__ in,
                                  float4* __restrict__ out, int n4)
{
    int i = blockIdx.x * blockDim.x + threadIdx.x;
    if (i >= n4) return;
    float4 v = in[i];
    out[i] = make_float4(__uint_as_float(f2tf32(v.x)), __uint_as_float(f2tf32(v.y)),
                         __uint_as_float(f2tf32(v.z)), __uint_as_float(f2tf32(v.w)));
}

// ---------------------------------------------------------------------------
// tf32 mma.sync GEMM, cp.async 3-stage pipeline.
// C[M,N] = A[M,K] @ B[N,K]^T + bias[N], operands pre-rounded to tf32.
// CTA 128x128, BK=32, 8 warps (2x4), warp tile 64x32.
// Stage: A[128][32] + B[128][32] floats = 32KB; 3 stages = 96KB dynamic smem.
// Row = 128B, 16B-chunk XOR-(row&7) swizzle -> conflict-free ldmatrix.
// ---------------------------------------------------------------------------
#define GSTAGE 32768
#define GB_OFF 16384
__global__ __launch_bounds__(256) void gemm_tf32_pipe(
    const float* __restrict__ A, const float* __restrict__ B,
    const float* __restrict__ bias, float* __restrict__ C,
    int N, int K)
{
    extern __shared__ char smem[];
    const uint32_t sb = smem_u32(smem);

    const int tid  = threadIdx.x;
    const int wid  = tid >> 5, lane = tid & 31;
    const int gid  = lane >> 2, tig = lane & 3;
    const int wm   = wid >> 2, wn = wid & 3;
    const int m0   = blockIdx.y * 128;
    const int n0   = blockIdx.x * 128;

    const int rowb = (lane & 7) + ((lane >> 4) << 3);
    const uint32_t swz7 = (uint32_t)(rowb & 7);
    const uint32_t chp  = (uint32_t)((lane >> 3) & 1);

    // load mapping: 4 float4s per thread per matrix per tile
    const int lr4 = tid >> 3;          // base row / 16 ... idx>>3 below
    const int lc4 = tid & 7;           // chunk 0..7
    const uint32_t ldst = ((uint32_t)((lc4 ^ (lr4 & 7))) << 4) + (uint32_t)lr4 * 128;
    const float* Ap = A + (size_t)(m0 + lr4) * K + lc4 * 4;
    const float* Bp = B + (size_t)(n0 + lr4) * K + lc4 * 4;

    float acc[4][4][4];
#pragma unroll
    for (int mi = 0; mi < 4; mi++)
#pragma unroll
        for (int nj = 0; nj < 4; nj++)
#pragma unroll
            for (int t = 0; t < 4; t++) acc[mi][nj][t] = 0.0f;

    const int KT = K >> 5;   // BK=32

    // prologue: stages 0,1
#pragma unroll
    for (int s = 0; s < 2; s++) {
        const uint32_t base = sb + s * GSTAGE;
        const int kc = s * 32;
#pragma unroll
        for (int p = 0; p < 4; p++) {   // rows lr4 + p*32
            cpa16(base + ldst + p * 32 * 128, Ap + (size_t)(p * 32) * K + kc);
            cpa16(base + GB_OFF + ldst + p * 32 * 128, Bp + (size_t)(p * 32) * K + kc);
        }
        cpa_commit();
    }
    cpa_wait<1>();
    __syncthreads();

    for (int kt = 0; kt < KT; kt++) {
        // prefetch stage kt+2
        if (kt + 2 < KT) {
            const uint32_t base = sb + ((kt + 2) % 3) * GSTAGE;
            const int kc = (kt + 2) * 32;
#pragma unroll
            for (int p = 0; p < 4; p++) {
                cpa16(base + ldst + p * 32 * 128, Ap + (size_t)(p * 32) * K + kc);
                cpa16(base + GB_OFF + ldst + p * 32 * 128, Bp + (size_t)(p * 32) * K + kc);
            }
        }
        cpa_commit();

        // compute stage kt%3
        const uint32_t abase = sb + (kt % 3) * GSTAGE;
        const uint32_t bbase = abase + GB_OFF;
#pragma unroll
        for (int ks = 0; ks < 4; ks++) {
            const uint32_t lo = (((2u * ks + chp) ^ swz7) << 4);
            uint32_t a[4][4], b[4][2];
#pragma unroll
            for (int mi = 0; mi < 4; mi++) {
                uint32_t r0, r1, r2, r3;
                ldsm4(abase + (uint32_t)(wm * 64 + mi * 16 + rowb) * 128 + lo,
                      r0, r1, r2, r3);
                a[mi][0] = r0; a[mi][1] = r2; a[mi][2] = r1; a[mi][3] = r3;
            }
#pragma unroll
            for (int njp = 0; njp < 2; njp++) {
                uint32_t r0, r1, r2, r3;
                ldsm4(bbase + (uint32_t)(wn * 32 + njp * 16 + rowb) * 128 + lo,
                      r0, r1, r2, r3);
                b[2 * njp][0] = r0;     b[2 * njp][1] = r1;
                b[2 * njp + 1][0] = r2; b[2 * njp + 1][1] = r3;
            }
#pragma unroll
            for (int mi = 0; mi < 4; mi++)
#pragma unroll
                for (int nj = 0; nj < 4; nj++)
                    mma_16x8x8(acc[mi][nj], a[mi], b[nj]);
        }

        cpa_wait<1>();      // stage kt+1 data landed
        __syncthreads();    // all warps done reading stage kt before overwrite
    }

    const float* bp = bias + n0 + wn * 32;
#pragma unroll
    for (int nj = 0; nj < 4; nj++) {
        int c = nj * 8 + 2 * tig;
        float2 bb = *(const float2*)(bp + c);
#pragma unroll
        for (int mi = 0; mi < 4; mi++) {
            int r = m0 + wm * 64 + mi * 16 + gid;
            float* dst = C + (size_t)r * N + n0 + wn * 32 + c;
            *(float2*)dst = make_float2(acc[mi][nj][0] + bb.x, acc[mi][nj][1] + bb.y);
            *(float2*)(dst + 8 * N) =
                make_float2(acc[mi][nj][2] + bb.x, acc[mi][nj][3] + bb.y);
        }
    }
}

// ---------------------------------------------------------------------------
// RoPE tables + apply (unchanged).
// ---------------------------------------------------------------------------
__global__ void cs_table_kernel(const int* __restrict__ positions)
{
    int idx = blockIdx.x * blockDim.x + threadIdx.x;
    if (idx >= S_LEN * 64) return;
    int i = idx & 63;
    int s = idx >> 6;
    float pos = (float)positions[s];
    double e = (double)(2 * i) / 128.0;
    float invf = (float)(1.0 / pow(1.0e6, e));
    float freq = pos * invf;
    g_cos[idx] = (float)cos((double)freq);
    g_sin[idx] = (float)sin((double)freq);
}

__global__ void rope_apply_kernel()
{
    int idx = blockIdx.x * blockDim.x + threadIdx.x;
    int i = idx & 63;
    int t = idx >> 6;
    int slot = t % 5;
    t /= 5;
    int kvh = t & 7;
    int s = t >> 3;
    float c  = g_cos[(s << 6) | i];
    float sn = g_sin[(s << 6) | i];
    size_t base = (size_t)s * QKV_N + kvh * 768 + slot * 128 + i;
    float x1 = g_qkv[base];
    float x2 = g_qkv[base + 64];
    g_qkv[base]      = x1 * c - x2 * sn;
    g_qkv[base + 64] = x2 * c + x1 * sn;
}

// ---------------------------------------------------------------------------
// Tensor-core blocksparse flash attention (round-4 version; output now
// tf32-rounded so the dense-proj GEMM needs no conversion).
// ---------------------------------------------------------------------------
#define ATT_QS 0
#define ATT_KS 32768
#define ATT_VT 65536
#define ATT_PS 98304
#define ATT_SMEM 114688

__global__ __launch_bounds__(128) void attn_tc_kernel(float* __restrict__ out)
{
    extern __shared__ char smem[];
    const uint32_t sb = smem_u32(smem);
    const int tid = threadIdx.x, lane = tid & 31, w = tid >> 5;
    const int gid = lane >> 2, tig = lane & 3;
    const int qb = blockIdx.x, h = blockIdx.y;
    const int kvh = h >> 2, slot = h & 3;
    const int q0 = qb * 64;
    const size_t qoff = (size_t)kvh * 768 + slot * 128;
    const size_t koff = (size_t)kvh * 768 + 512;
    const size_t voff = (size_t)kvh * 768 + 640;

    const int rowb = (lane & 7) + ((lane >> 4) << 3);
    const uint32_t swz7 = (uint32_t)(rowb & 7);
    const uint32_t chp  = (uint32_t)((lane >> 3) & 1);
    const int Rw = w * 16;

#pragma unroll
    for (int i = 0; i < 16; i++) {
        int idx = tid + i * 128;
        int r = idx >> 5, c = idx & 31;
        float4 v = *(const float4*)(g_qkv + (size_t)(q0 + r) * QKV_N + qoff + c * 4);
        uint32_t off = (uint32_t)r * 512 + ((uint32_t)(c >> 3) << 7)
                     + ((((uint32_t)(c & 7)) ^ (uint32_t)(r & 7)) << 4);
        *(uint4*)(smem + ATT_QS + off) =
            make_uint4(f2tf32(v.x), f2tf32(v.y), f2tf32(v.z), f2tf32(v.w));
    }

    float Oa[16][4];
#pragma unroll
    for (int nf = 0; nf < 16; nf++)
#pragma unroll
        for (int t = 0; t < 4; t++) Oa[nf][t] = 0.0f;
    float m0r = -1e30f, m1r = -1e30f, l0 = 0.0f, l1 = 0.0f;

    for (int kb = 0; kb <= qb; kb++) {
        if (!(((qb - kb) < 16) || (((kb + h + 1) & 7) == 0))) continue;
        const int k0 = kb * 64;
        __syncthreads();
#pragma unroll
        for (int i = 0; i < 16; i++) {
            int idx = tid + i * 128;
            int r = idx >> 5, c = idx & 31;
            float4 v = *(const float4*)(g_qkv + (size_t)(k0 + r) * QKV_N + koff + c * 4);
            uint32_t off = (uint32_t)r * 512 + ((uint32_t)(c >> 3) << 7)
                         + ((((uint32_t)(c & 7)) ^ (uint32_t)(r & 7)) << 4);
            *(uint4*)(smem + ATT_KS + off) =
                make_uint4(f2tf32(v.x), f2tf32(v.y), f2tf32(v.z), f2tf32(v.w));
        }
#pragma unroll
        for (int i = 0; i < 16; i++) {
            int idx = tid + i * 128;
            int r = idx & 63, c = idx >> 6;
            float4 v = *(const float4*)(g_qkv + (size_t)(k0 + r) * QKV_N + voff + c * 4);
            uint32_t vv[4] = {f2tf32(v.x), f2tf32(v.y), f2tf32(v.z), f2tf32(v.w)};
#pragma unroll
            for (int j = 0; j < 4; j++) {
                int d = 4 * c + j;
                uint32_t off = (uint32_t)d * 256 + (((uint32_t)r >> 5) << 7)
                    + (((((uint32_t)r >> 2) & 7) ^ (uint32_t)(d & 7)) << 4)
                    + (uint32_t)(r & 3) * 4;
                *(uint32_t*)(smem + ATT_VT + off) = vv[j];
            }
        }
        __syncthreads();

        float Sa[8][4];
#pragma unroll
        for (int nj = 0; nj < 8; nj++)
#pragma unroll
            for (int t = 0; t < 4; t++) Sa[nj][t] = 0.0f;
#pragma unroll
        for (int ks2 = 0; ks2 < 16; ks2++) {
            uint32_t ch = 2u * ks2 + chp;
            uint32_t hi = (ch >> 3) << 7, lo = ((ch & 7) ^ swz7) << 4;
            uint32_t r0, r1, r2, r3;
            ldsm4(sb + ATT_QS + (uint32_t)(Rw + rowb) * 512 + hi + lo, r0, r1, r2, r3);
            uint32_t Af[4] = {r0, r2, r1, r3};
#pragma unroll
            for (int njp = 0; njp < 4; njp++) {
                uint32_t b0, b1, b2, b3;
                ldsm4(sb + ATT_KS + (uint32_t)(njp * 16 + rowb) * 512 + hi + lo,
                      b0, b1, b2, b3);
                uint32_t B0[2] = {b0, b1}, B1[2] = {b2, b3};
                mma_16x8x8(Sa[2 * njp], Af, B0);
                mma_16x8x8(Sa[2 * njp + 1], Af, B1);
            }
        }

        const bool diag = (kb == qb);
        const int r0l = Rw + gid, r1l = r0l + 8;
        float mx0 = -1e30f, mx1 = -1e30f;
#pragma unroll
        for (int nj = 0; nj < 8; nj++) {
            int c0 = nj * 8 + 2 * tig;
            float v0 = Sa[nj][0] * SCALE_ATT;
            float v1 = Sa[nj][1] * SCALE_ATT;
            float v2 = Sa[nj][2] * SCALE_ATT;
            float v3 = Sa[nj][3] * SCALE_ATT;
            if (diag) {
                if (c0 > r0l)     v0 = -1e30f;
                if (c0 + 1 > r0l) v1 = -1e30f;
                if (c0 > r1l)     v2 = -1e30f;
                if (c0 + 1 > r1l) v3 = -1e30f;
            }
            Sa[nj][0] = v0; Sa[nj][1] = v1; Sa[nj][2] = v2; Sa[nj][3] = v3;
            mx0 = fmaxf(mx0, fmaxf(v0, v1));
            mx1 = fmaxf(mx1, fmaxf(v2, v3));
        }
        mx0 = fmaxf(mx0, __shfl_xor_sync(0xffffffffu, mx0, 1));
        mx0 = fmaxf(mx0, __shfl_xor_sync(0xffffffffu, mx0, 2));
        mx1 = fmaxf(mx1, __shfl_xor_sync(0xffffffffu, mx1, 1));
        mx1 = fmaxf(mx1, __shfl_xor_sync(0xffffffffu, mx1, 2));
        const float mn0 = fmaxf(m0r, mx0), mn1 = fmaxf(m1r, mx1);
        const float corr0 = __expf(m0r - mn0), corr1 = __expf(m1r - mn1);
        float s0 = 0.0f, s1 = 0.0f;
#pragma unroll
        for (int nj = 0; nj < 8; nj++) {
            float p0 = __expf(Sa[nj][0] - mn0);
            float p1 = __expf(Sa[nj][1] - mn0);
            float p2 = __expf(Sa[nj][2] - mn1);
            float p3 = __expf(Sa[nj][3] - mn1);
            s0 += p0 + p1; s1 += p2 + p3;
            int col = nj * 8 + 2 * tig;
            uint32_t ch = (uint32_t)col >> 2;
            uint32_t base = ((ch >> 3) << 7) + (((ch & 7) ^ (uint32_t)(r0l & 7)) << 4)
                          + ((uint32_t)col & 3) * 4;
            *(uint2*)(smem + ATT_PS + (uint32_t)r0l * 256 + base) =
                make_uint2(f2tf32(p0), f2tf32(p1));
            *(uint2*)(smem + ATT_PS + (uint32_t)r1l * 256 + base) =
                make_uint2(f2tf32(p2), f2tf32(p3));
        }
        s0 += __shfl_xor_sync(0xffffffffu, s0, 1);
        s0 += __shfl_xor_sync(0xffffffffu, s0, 2);
        s1 += __shfl_xor_sync(0xffffffffu, s1, 1);
        s1 += __shfl_xor_sync(0xffffffffu, s1, 2);
        l0 = l0 * corr0 + s0; l1 = l1 * corr1 + s1;
        m0r = mn0; m1r = mn1;
#pragma unroll
        for (int nf = 0; nf < 16; nf++) {
            Oa[nf][0] *= corr0; Oa[nf][1] *= corr0;
            Oa[nf][2] *= corr1; Oa[nf][3] *= corr1;
        }
        __syncwarp();

#pragma unroll
        for (int kss = 0; kss < 8; kss++) {
            uint32_t ch = 2u * kss + chp;
            uint32_t hi = (ch >> 3) << 7, lo = ((ch & 7) ^ swz7) << 4;
            uint32_t r0, r1, r2, r3;
            ldsm4(sb + ATT_PS + (uint32_t)(Rw + rowb) * 256 + hi + lo, r0, r1, r2, r3);
            uint32_t Af[4] = {r0, r2, r1, r3};
#pragma unroll
            for (int nfp = 0; nfp < 8; nfp++) {
                uint32_t b0, b1, b2, b3;
                ldsm4(sb + ATT_VT + (uint32_t)(nfp * 16 + rowb) * 256 + hi + lo,
                      b0, b1, b2, b3);
                uint32_t B0[2] = {b0, b1}, B1[2] = {b2, b3};
                mma_16x8x8(Oa[2 * nfp], Af, B0);
                mma_16x8x8(Oa[2 * nfp + 1], Af, B1);
            }
        }
        __syncwarp();
    }

    // epilogue: tf32-rounded output (dense-proj A operand pre-rounded)
    const float i0 = 1.0f / l0, i1 = 1.0f / l1;
    const int gr0 = q0 + Rw + gid;
    float* d0 = out + (size_t)gr0 * OUT_N + h * HD;
    float* d1 = d0 + (size_t)8 * OUT_N;
#pragma unroll
    for (int nf = 0; nf < 16; nf++) {
        int c = nf * 8 + 2 * tig;
        *(float2*)(d0 + c) =
            make_float2(__uint_as_float(f2tf32(Oa[nf][0] * i0)),
                        __uint_as_float(f2tf32(Oa[nf][1] * i0)));
        *(float2*)(d1 + c) =
            make_float2(__uint_as_float(f2tf32(Oa[nf][2] * i1)),
                        __uint_as_float(f2tf32(Oa[nf][3] * i1)));
    }
}

// ---------------------------------------------------------------------------
extern "C" void kernel_launch(void* const* d_in, const int* in_sizes, int n_in,
                              void* d_out, int out_size)
{
    const int*   positions = (const int*)  d_in[0];
    const float* hidden    = (const float*)d_in[1];
    const float* w_qkv     = (const float*)d_in[2];
    const float* b_qkv     = (const float*)d_in[3];
    const float* w_dense   = (const float*)d_in[4];
    const float* b_dense   = (const float*)d_in[5];
    float* out = (float*)d_out;

    float *qkv_p, *att_p, *hid_t, *wqkv_t, *wd_t;
    cudaGetSymbolAddress((void**)&qkv_p, g_qkv);
    cudaGetSymbolAddress((void**)&att_p, g_att);
    cudaGetSymbolAddress((void**)&hid_t, g_hid_t);
    cudaGetSymbolAddress((void**)&wqkv_t, g_wqkv_t);
    cudaGetSymbolAddress((void**)&wd_t, g_wd_t);

    cudaFuncSetAttribute(attn_tc_kernel,
                         cudaFuncAttributeMaxDynamicSharedMemorySize, ATT_SMEM);
    cudaFuncSetAttribute(gemm_tf32_pipe,
                         cudaFuncAttributeMaxDynamicSharedMemorySize, 3 * GSTAGE);

    // 0) pre-round operands to tf32
    {
        int n4;
        n4 = S_LEN * HIDDEN / 4;
        round_tf32_kernel<<<(n4 + 255) / 256, 256>>>((const float4*)hidden,
                                                     (float4*)hid_t, n4);
        n4 = QKV_N * HIDDEN / 4;
        round_tf32_kernel<<<(n4 + 255) / 256, 256>>>((const float4*)w_qkv,
                                                     (float4*)wqkv_t, n4);
        n4 = HIDDEN * HIDDEN / 4;
        round_tf32_kernel<<<(n4 + 255) / 256, 256>>>((const float4*)w_dense,
                                                     (float4*)wd_t, n4);
    }
    // 1) QKV = hidden @ w_qkv^T + b_qkv
    gemm_tf32_pipe<<<dim3(QKV_N / 128, S_LEN / 128), 256, 3 * GSTAGE>>>(
        hid_t, wqkv_t, b_qkv, qkv_p, QKV_N, HIDDEN);
    // 2) RoPE
    cs_table_kernel<<<(S_LEN * 64 + 255) / 256, 256>>>(positions);
    rope_apply_kernel<<<(S_LEN * NKV * 5 * 64) / 256, 256>>>();
    // 3) blocksparse attention (tensor cores)
    attn_tc_kernel<<<dim3(32, 32), 128, ATT_SMEM>>>(att_p);
    // 4) out = g_att @ w_dense^T + b_dense
    gemm_tf32_pipe<<<dim3(OUT_N / 128, S_LEN / 128), 256, 3 * GSTAGE>>>(
        att_p, wd_t, b_dense, out, OUT_N, HIDDEN);
}

// round 6
// speedup vs baseline: 3.3996x; 1.0250x over previous
#include <cuda_runtime.h>
#include <cstdint>
#include <math.h>

#define S_LEN   2048
#define HIDDEN  4096
#define NHEADS  32
#define NKV     8
#define HD      128
#define QPK     4
#define QKV_N   6144          // NKV*(QPK+2)*HD
#define OUT_N   4096          // NHEADS*HD
#define SCALE_ATT 0.0078125f  // 1/HD

// ---------------- scratch (device globals: no allocations allowed) ----------
__device__ float g_qkv[S_LEN * QKV_N];        // 50 MB
__device__ float g_att[S_LEN * OUT_N];        // 32 MB
__device__ float g_cos[S_LEN * 64];
__device__ float g_sin[S_LEN * 64];
__device__ float g_hid_t[S_LEN * HIDDEN];     // 32 MB  (tf32-rounded hidden)
__device__ float g_wqkv_t[QKV_N * HIDDEN];    // 100 MB (tf32-rounded w_qkv)
__device__ float g_wd_t[HIDDEN * HIDDEN];     // 64 MB  (tf32-rounded w_dense)

// ---------------- helpers ---------------------------------------------------
__device__ __forceinline__ uint32_t smem_u32(const void* p) {
    uint32_t a;
    asm("{ .reg .u64 t; cvta.to.shared.u64 t, %1; cvt.u32.u64 %0, t; }"
        : "=r"(a) : "l"(p));
    return a;
}
__device__ __forceinline__ uint32_t f2tf32(float x) {
    uint32_t u;
    asm("cvt.rna.tf32.f32 %0, %1;" : "=r"(u) : "f"(x));
    return u;
}
__device__ __forceinline__ void mma_16x8x8(float* c, const uint32_t* a,
                                           const uint32_t* b) {
    asm volatile(
        "mma.sync.aligned.m16n8k8.row.col.f32.tf32.tf32.f32 "
        "{%0,%1,%2,%3}, {%4,%5,%6,%7}, {%8,%9}, {%0,%1,%2,%3};\n"
        : "+f"(c[0]), "+f"(c[1]), "+f"(c[2]), "+f"(c[3])
        : "r"(a[0]), "r"(a[1]), "r"(a[2]), "r"(a[3]), "r"(b[0]), "r"(b[1]));
}
// 16x8 b32 tile via four 8x8 b16 matrices (b32 elem (t/4, t%4) per sub-tile).
__device__ __forceinline__ void ldsm4(uint32_t addr, uint32_t& r0, uint32_t& r1,
                                      uint32_t& r2, uint32_t& r3) {
    asm volatile("ldmatrix.sync.aligned.m8n8.x4.shared.b16 {%0,%1,%2,%3}, [%4];"
                 : "=r"(r0), "=r"(r1), "=r"(r2), "=r"(r3) : "r"(addr));
}
__device__ __forceinline__ void cpa16(uint32_t dst, const void* src) {
    asm volatile("cp.async.cg.shared.global [%0], [%1], 16;" :: "r"(dst), "l"(src));
}
__device__ __forceinline__ void cpa_commit() {
    asm volatile("cp.async.commit_group;" ::: "memory");
}
template <int N>
__device__ __forceinline__ void cpa_wait() {
    asm volatile("cp.async.wait_group %0;" :: "n"(N) : "memory");
}

// ---------------------------------------------------------------------------
// tf32-rounding prep pass.
// ---------------------------------------------------------------------------
__global__ void round_tf32_kernel(const float4* __restrict__ in,
                                  float4* __restrict__ out, int n4)
{
    int i = blockIdx.x * blockDim.x + threadIdx.x;
    if (i >= n4) return;
    float4 v = in[i];
    out[i] = make_float4(__uint_as_float(f2tf32(v.x)), __uint_as_float(f2tf32(v.y)),
                         __uint_as_float(f2tf32(v.z)), __uint_as_float(f2tf32(v.w)));
}

// ---------------------------------------------------------------------------
// tf32 mma.sync GEMM, cp.async 3-stage pipeline, 2 CTAs/SM.
// C[M,N] = A[M,K] @ B[N,K]^T + bias[N], operands pre-rounded to tf32.
// CTA 128x128, BK=32, 8 warps (2x4), warp tile 64x32. 96KB dynamic smem.
// ---------------------------------------------------------------------------
#define GSTAGE 32768
#define GB_OFF 16384
__global__ __launch_bounds__(256, 2) void gemm_tf32_pipe(
    const float* __restrict__ A, const float* __restrict__ B,
    const float* __restrict__ bias, float* __restrict__ C,
    int N, int K)
{
    extern __shared__ char smem[];
    const uint32_t sb = smem_u32(smem);

    const int tid  = threadIdx.x;
    const int wid  = tid >> 5, lane = tid & 31;
    const int gid  = lane >> 2, tig = lane & 3;
    const int wm   = wid >> 2, wn = wid & 3;
    const int m0   = blockIdx.y * 128;
    const int n0   = blockIdx.x * 128;

    const int rowb = (lane & 7) + ((lane >> 4) << 3);
    const uint32_t swz7 = (uint32_t)(rowb & 7);
    const uint32_t chp  = (uint32_t)((lane >> 3) & 1);

    const int lr4 = tid >> 3;
    const int lc4 = tid & 7;
    const uint32_t ldst = ((uint32_t)((lc4 ^ (lr4 & 7))) << 4) + (uint32_t)lr4 * 128;
    const float* Ap = A + (size_t)(m0 + lr4) * K + lc4 * 4;
    const float* Bp = B + (size_t)(n0 + lr4) * K + lc4 * 4;

    float acc[4][4][4];
#pragma unroll
    for (int mi = 0; mi < 4; mi++)
#pragma unroll
        for (int nj = 0; nj < 4; nj++)
#pragma unroll
            for (int t = 0; t < 4; t++) acc[mi][nj][t] = 0.0f;

    const int KT = K >> 5;

#pragma unroll
    for (int s = 0; s < 2; s++) {
        const uint32_t base = sb + s * GSTAGE;
        const int kc = s * 32;
#pragma unroll
        for (int p = 0; p < 4; p++) {
            cpa16(base + ldst + p * 32 * 128, Ap + (size_t)(p * 32) * K + kc);
            cpa16(base + GB_OFF + ldst + p * 32 * 128, Bp + (size_t)(p * 32) * K + kc);
        }
        cpa_commit();
    }
    cpa_wait<1>();
    __syncthreads();

    for (int kt = 0; kt < KT; kt++) {
        if (kt + 2 < KT) {
            const uint32_t base = sb + ((kt + 2) % 3) * GSTAGE;
            const int kc = (kt + 2) * 32;
#pragma unroll
            for (int p = 0; p < 4; p++) {
                cpa16(base + ldst + p * 32 * 128, Ap + (size_t)(p * 32) * K + kc);
                cpa16(base + GB_OFF + ldst + p * 32 * 128, Bp + (size_t)(p * 32) * K + kc);
            }
        }
        cpa_commit();

        const uint32_t abase = sb + (kt % 3) * GSTAGE;
        const uint32_t bbase = abase + GB_OFF;
#pragma unroll
        for (int ks = 0; ks < 4; ks++) {
            const uint32_t lo = (((2u * ks + chp) ^ swz7) << 4);
            uint32_t a[4][4], b[4][2];
#pragma unroll
            for (int mi = 0; mi < 4; mi++) {
                uint32_t r0, r1, r2, r3;
                ldsm4(abase + (uint32_t)(wm * 64 + mi * 16 + rowb) * 128 + lo,
                      r0, r1, r2, r3);
                a[mi][0] = r0; a[mi][1] = r2; a[mi][2] = r1; a[mi][3] = r3;
            }
#pragma unroll
            for (int njp = 0; njp < 2; njp++) {
                uint32_t r0, r1, r2, r3;
                ldsm4(bbase + (uint32_t)(wn * 32 + njp * 16 + rowb) * 128 + lo,
                      r0, r1, r2, r3);
                b[2 * njp][0] = r0;     b[2 * njp][1] = r1;
                b[2 * njp + 1][0] = r2; b[2 * njp + 1][1] = r3;
            }
#pragma unroll
            for (int mi = 0; mi < 4; mi++)
#pragma unroll
                for (int nj = 0; nj < 4; nj++)
                    mma_16x8x8(acc[mi][nj], a[mi], b[nj]);
        }

        cpa_wait<1>();
        __syncthreads();
    }

    const float* bp = bias + n0 + wn * 32;
#pragma unroll
    for (int nj = 0; nj < 4; nj++) {
        int c = nj * 8 + 2 * tig;
        float2 bb = *(const float2*)(bp + c);
#pragma unroll
        for (int mi = 0; mi < 4; mi++) {
            int r = m0 + wm * 64 + mi * 16 + gid;
            float* dst = C + (size_t)r * N + n0 + wn * 32 + c;
            *(float2*)dst = make_float2(acc[mi][nj][0] + bb.x, acc[mi][nj][1] + bb.y);
            *(float2*)(dst + 8 * N) =
                make_float2(acc[mi][nj][2] + bb.x, acc[mi][nj][3] + bb.y);
        }
    }
}

// ---------------------------------------------------------------------------
// RoPE tables + apply (unchanged).
// ---------------------------------------------------------------------------
__global__ void cs_table_kernel(const int* __restrict__ positions)
{
    int idx = blockIdx.x * blockDim.x + threadIdx.x;
    if (idx >= S_LEN * 64) return;
    int i = idx & 63;
    int s = idx >> 6;
    float pos = (float)positions[s];
    double e = (double)(2 * i) / 128.0;
    float invf = (float)(1.0 / pow(1.0e6, e));
    float freq = pos * invf;
    g_cos[idx] = (float)cos((double)freq);
    g_sin[idx] = (float)sin((double)freq);
}

__global__ void rope_apply_kernel()
{
    int idx = blockIdx.x * blockDim.x + threadIdx.x;
    int i = idx & 63;
    int t = idx >> 6;
    int slot = t % 5;
    t /= 5;
    int kvh = t & 7;
    int s = t >> 3;
    float c  = g_cos[(s << 6) | i];
    float sn = g_sin[(s << 6) | i];
    size_t base = (size_t)s * QKV_N + kvh * 768 + slot * 128 + i;
    float x1 = g_qkv[base];
    float x2 = g_qkv[base + 64];
    g_qkv[base]      = x1 * c - x2 * sn;
    g_qkv[base + 64] = x2 * c + x1 * sn;
}

// ---------------------------------------------------------------------------
// Tensor-core blocksparse flash attention, 2 CTAs/SM.
// Ps OVERLAYS Ks (Ks dead after the QK^T MMAs each iteration; extra barrier
// between QK^T reads and Ps writes makes the overlay safe). smem 96KB.
// ---------------------------------------------------------------------------
#define ATT_QS 0
#define ATT_KS 32768
#define ATT_VT 65536
#define ATT_PS 32768           // overlays Ks
#define ATT_SMEM 98304

__global__ __launch_bounds__(128, 2) void attn_tc_kernel(float* __restrict__ out)
{
    extern __shared__ char smem[];
    const uint32_t sb = smem_u32(smem);
    const int tid = threadIdx.x, lane = tid & 31, w = tid >> 5;
    const int gid = lane >> 2, tig = lane & 3;
    const int qb = blockIdx.x, h = blockIdx.y;
    const int kvh = h >> 2, slot = h & 3;
    const int q0 = qb * 64;
    const size_t qoff = (size_t)kvh * 768 + slot * 128;
    const size_t koff = (size_t)kvh * 768 + 512;
    const size_t voff = (size_t)kvh * 768 + 640;

    const int rowb = (lane & 7) + ((lane >> 4) << 3);
    const uint32_t swz7 = (uint32_t)(rowb & 7);
    const uint32_t chp  = (uint32_t)((lane >> 3) & 1);
    const int Rw = w * 16;

#pragma unroll
    for (int i = 0; i < 16; i++) {
        int idx = tid + i * 128;
        int r = idx >> 5, c = idx & 31;
        float4 v = *(const float4*)(g_qkv + (size_t)(q0 + r) * QKV_N + qoff + c * 4);
        uint32_t off = (uint32_t)r * 512 + ((uint32_t)(c >> 3) << 7)
                     + ((((uint32_t)(c & 7)) ^ (uint32_t)(r & 7)) << 4);
        *(uint4*)(smem + ATT_QS + off) =
            make_uint4(f2tf32(v.x), f2tf32(v.y), f2tf32(v.z), f2tf32(v.w));
    }

    float Oa[16][4];
#pragma unroll
    for (int nf = 0; nf < 16; nf++)
#pragma unroll
        for (int t = 0; t < 4; t++) Oa[nf][t] = 0.0f;
    float m0r = -1e30f, m1r = -1e30f, l0 = 0.0f, l1 = 0.0f;

    for (int kb = 0; kb <= qb; kb++) {
        if (!(((qb - kb) < 16) || (((kb + h + 1) & 7) == 0))) continue;
        const int k0 = kb * 64;
        __syncthreads();   // prior PV done reading Ps(=Ks region) / Vt
#pragma unroll
        for (int i = 0; i < 16; i++) {
            int idx = tid + i * 128;
            int r = idx >> 5, c = idx & 31;
            float4 v = *(const float4*)(g_qkv + (size_t)(k0 + r) * QKV_N + koff + c * 4);
            uint32_t off = (uint32_t)r * 512 + ((uint32_t)(c >> 3) << 7)
                         + ((((uint32_t)(c & 7)) ^ (uint32_t)(r & 7)) << 4);
            *(uint4*)(smem + ATT_KS + off) =
                make_uint4(f2tf32(v.x), f2tf32(v.y), f2tf32(v.z), f2tf32(v.w));
        }
#pragma unroll
        for (int i = 0; i < 16; i++) {
            int idx = tid + i * 128;
            int r = idx & 63, c = idx >> 6;
            float4 v = *(const float4*)(g_qkv + (size_t)(k0 + r) * QKV_N + voff + c * 4);
            uint32_t vv[4] = {f2tf32(v.x), f2tf32(v.y), f2tf32(v.z), f2tf32(v.w)};
#pragma unroll
            for (int j = 0; j < 4; j++) {
                int d = 4 * c + j;
                uint32_t off = (uint32_t)d * 256 + (((uint32_t)r >> 5) << 7)
                    + (((((uint32_t)r >> 2) & 7) ^ (uint32_t)(d & 7)) << 4)
                    + (uint32_t)(r & 3) * 4;
                *(uint32_t*)(smem + ATT_VT + off) = vv[j];
            }
        }
        __syncthreads();

        // ---- S = Q @ K^T ----
        float Sa[8][4];
#pragma unroll
        for (int nj = 0; nj < 8; nj++)
#pragma unroll
            for (int t = 0; t < 4; t++) Sa[nj][t] = 0.0f;
#pragma unroll
        for (int ks2 = 0; ks2 < 16; ks2++) {
            uint32_t ch = 2u * ks2 + chp;
            uint32_t hi = (ch >> 3) << 7, lo = ((ch & 7) ^ swz7) << 4;
            uint32_t r0, r1, r2, r3;
            ldsm4(sb + ATT_QS + (uint32_t)(Rw + rowb) * 512 + hi + lo, r0, r1, r2, r3);
            uint32_t Af[4] = {r0, r2, r1, r3};
#pragma unroll
            for (int njp = 0; njp < 4; njp++) {
                uint32_t b0, b1, b2, b3;
                ldsm4(sb + ATT_KS + (uint32_t)(njp * 16 + rowb) * 512 + hi + lo,
                      b0, b1, b2, b3);
                uint32_t B0[2] = {b0, b1}, B1[2] = {b2, b3};
                mma_16x8x8(Sa[2 * njp], Af, B0);
                mma_16x8x8(Sa[2 * njp + 1], Af, B1);
            }
        }
        __syncthreads();   // all warps done reading Ks before Ps overlays it

        const bool diag = (kb == qb);
        const int r0l = Rw + gid, r1l = r0l + 8;
        float mx0 = -1e30f, mx1 = -1e30f;
#pragma unroll
        for (int nj = 0; nj < 8; nj++) {
            int c0 = nj * 8 + 2 * tig;
            float v0 = Sa[nj][0] * SCALE_ATT;
            float v1 = Sa[nj][1] * SCALE_ATT;
            float v2 = Sa[nj][2] * SCALE_ATT;
            float v3 = Sa[nj][3] * SCALE_ATT;
            if (diag) {
                if (c0 > r0l)     v0 = -1e30f;
                if (c0 + 1 > r0l) v1 = -1e30f;
                if (c0 > r1l)     v2 = -1e30f;
                if (c0 + 1 > r1l) v3 = -1e30f;
            }
            Sa[nj][0] = v0; Sa[nj][1] = v1; Sa[nj][2] = v2; Sa[nj][3] = v3;
            mx0 = fmaxf(mx0, fmaxf(v0, v1));
            mx1 = fmaxf(mx1, fmaxf(v2, v3));
        }
        mx0 = fmaxf(mx0, __shfl_xor_sync(0xffffffffu, mx0, 1));
        mx0 = fmaxf(mx0, __shfl_xor_sync(0xffffffffu, mx0, 2));
        mx1 = fmaxf(mx1, __shfl_xor_sync(0xffffffffu, mx1, 1));
        mx1 = fmaxf(mx1, __shfl_xor_sync(0xffffffffu, mx1, 2));
        const float mn0 = fmaxf(m0r, mx0), mn1 = fmaxf(m1r, mx1);
        const float corr0 = __expf(m0r - mn0), corr1 = __expf(m1r - mn1);
        float s0 = 0.0f, s1 = 0.0f;
#pragma unroll
        for (int nj = 0; nj < 8; nj++) {
            float p0 = __expf(Sa[nj][0] - mn0);
            float p1 = __expf(Sa[nj][1] - mn0);
            float p2 = __expf(Sa[nj][2] - mn1);
            float p3 = __expf(Sa[nj][3] - mn1);
            s0 += p0 + p1; s1 += p2 + p3;
            int col = nj * 8 + 2 * tig;
            uint32_t ch = (uint32_t)col >> 2;
            uint32_t base = ((ch >> 3) << 7) + (((ch & 7) ^ (uint32_t)(r0l & 7)) << 4)
                          + ((uint32_t)col & 3) * 4;
            *(uint2*)(smem + ATT_PS + (uint32_t)r0l * 256 + base) =
                make_uint2(f2tf32(p0), f2tf32(p1));
            *(uint2*)(smem + ATT_PS + (uint32_t)r1l * 256 + base) =
                make_uint2(f2tf32(p2), f2tf32(p3));
        }
        s0 += __shfl_xor_sync(0xffffffffu, s0, 1);
        s0 += __shfl_xor_sync(0xffffffffu, s0, 2);
        s1 += __shfl_xor_sync(0xffffffffu, s1, 1);
        s1 += __shfl_xor_sync(0xffffffffu, s1, 2);
        l0 = l0 * corr0 + s0; l1 = l1 * corr1 + s1;
        m0r = mn0; m1r = mn1;
#pragma unroll
        for (int nf = 0; nf < 16; nf++) {
            Oa[nf][0] *= corr0; Oa[nf][1] *= corr0;
            Oa[nf][2] *= corr1; Oa[nf][3] *= corr1;
        }
        __syncthreads();   // Ps visible to all warps

        // ---- O += P @ V ----
#pragma unroll
        for (int kss = 0; kss < 8; kss++) {
            uint32_t ch = 2u * kss + chp;
            uint32_t hi = (ch >> 3) << 7, lo = ((ch & 7) ^ swz7) << 4;
            uint32_t r0, r1, r2, r3;
            ldsm4(sb + ATT_PS + (uint32_t)(Rw + rowb) * 256 + hi + lo, r0, r1, r2, r3);
            uint32_t Af[4] = {r0, r2, r1, r3};
#pragma unroll
            for (int nfp = 0; nfp < 8; nfp++) {
                uint32_t b0, b1, b2, b3;
                ldsm4(sb + ATT_VT + (uint32_t)(nfp * 16 + rowb) * 256 + hi + lo,
                      b0, b1, b2, b3);
                uint32_t B0[2] = {b0, b1}, B1[2] = {b2, b3};
                mma_16x8x8(Oa[2 * nfp], Af, B0);
                mma_16x8x8(Oa[2 * nfp + 1], Af, B1);
            }
        }
    }

    const float i0 = 1.0f / l0, i1 = 1.0f / l1;
    const int gr0 = q0 + Rw + gid;
    float* d0 = out + (size_t)gr0 * OUT_N + h * HD;
    float* d1 = d0 + (size_t)8 * OUT_N;
#pragma unroll
    for (int nf = 0; nf < 16; nf++) {
        int c = nf * 8 + 2 * tig;
        *(float2*)(d0 + c) =
            make_float2(__uint_as_float(f2tf32(Oa[nf][0] * i0)),
                        __uint_as_float(f2tf32(Oa[nf][1] * i0)));
        *(float2*)(d1 + c) =
            make_float2(__uint_as_float(f2tf32(Oa[nf][2] * i1)),
                        __uint_as_float(f2tf32(Oa[nf][3] * i1)));
    }
}

// ---------------------------------------------------------------------------
extern "C" void kernel_launch(void* const* d_in, const int* in_sizes, int n_in,
                              void* d_out, int out_size)
{
    const int*   positions = (const int*)  d_in[0];
    const float* hidden    = (const float*)d_in[1];
    const float* w_qkv     = (const float*)d_in[2];
    const float* b_qkv     = (const float*)d_in[3];
    const float* w_dense   = (const float*)d_in[4];
    const float* b_dense   = (const float*)d_in[5];
    float* out = (float*)d_out;

    float *qkv_p, *att_p, *hid_t, *wqkv_t, *wd_t;
    cudaGetSymbolAddress((void**)&qkv_p, g_qkv);
    cudaGetSymbolAddress((void**)&att_p, g_att);
    cudaGetSymbolAddress((void**)&hid_t, g_hid_t);
    cudaGetSymbolAddress((void**)&wqkv_t, g_wqkv_t);
    cudaGetSymbolAddress((void**)&wd_t, g_wd_t);

    cudaFuncSetAttribute(attn_tc_kernel,
                         cudaFuncAttributeMaxDynamicSharedMemorySize, ATT_SMEM);
    cudaFuncSetAttribute(gemm_tf32_pipe,
                         cudaFuncAttributeMaxDynamicSharedMemorySize, 3 * GSTAGE);

    // 0) pre-round operands to tf32
    {
        int n4;
        n4 = S_LEN * HIDDEN / 4;
        round_tf32_kernel<<<(n4 + 255) / 256, 256>>>((const float4*)hidden,
                                                     (float4*)hid_t, n4);
        n4 = QKV_N * HIDDEN / 4;
        round_tf32_kernel<<<(n4 + 255) / 256, 256>>>((const float4*)w_qkv,
                                                     (float4*)wqkv_t, n4);
        n4 = HIDDEN * HIDDEN / 4;
        round_tf32_kernel<<<(n4 + 255) / 256, 256>>>((const float4*)w_dense,
                                                     (float4*)wd_t, n4);
    }
    // 1) QKV = hidden @ w_qkv^T + b_qkv
    gemm_tf32_pipe<<<dim3(QKV_N / 128, S_LEN / 128), 256, 3 * GSTAGE>>>(
        hid_t, wqkv_t, b_qkv, qkv_p, QKV_N, HIDDEN);
    // 2) RoPE
    cs_table_kernel<<<(S_LEN * 64 + 255) / 256, 256>>>(positions);
    rope_apply_kernel<<<(S_LEN * NKV * 5 * 64) / 256, 256>>>();
    // 3) blocksparse attention (tensor cores)
    attn_tc_kernel<<<dim3(32, 32), 128, ATT_SMEM>>>(att_p);
    // 4) out = g_att @ w_dense^T + b_dense
    gemm_tf32_pipe<<<dim3(OUT_N / 128, S_LEN / 128), 256, 3 * GSTAGE>>>(
        att_p, wd_t, b_dense, out, OUT_N, HIDDEN);
}